// round 10
// baseline (speedup 1.0000x reference)
#include <cuda_runtime.h>
#include <cstdint>

// WCT: out[b] = alpha*x[b] + (1-alpha)*( M_b * (x[b]-mean_b) + mean_{perm[b]} )
// M_b = cov_{perm[b]}^{1/2} * cov_b^{-1/2}, roots via coupled Newton-Schulz.
// Folded: out = A_b * x + bias_b with A_b = alpha*I + (1-alpha)*M_b.
// R9: apply = 512 threads / 512px tile, 8px x 8ch per thread (B/FMA=1.0),
//     phase-split cp.async half-tile pipeline, k4-vectorized inner loop.
//     gram = R7 reg-prefetch version forced to 2 blocks/SM.

#define BATCH 16
#define HW 65536
#define NCH 64
#define GBLK 16                 // gram blocks per batch
#define GPIX (HW / GBLK)        // 4096 pixels per gram block
#define ABLK 16                 // apply blocks per batch
#define APIX (HW / ABLK)        // 4096 pixels per apply block
#define NS_ITERS 6
#define MS 68                   // padded row stride (floats) for 64x64 smem matrices
#define XS 68                   // padded row stride (floats) for pixel tiles
#define GT 288                  // gram threads: 8 pixel-groups x 36 upper tiles
#define AT 512                  // apply pixels per tile (= apply threads)

// ---- device scratch (static globals; allocation-free) ----
__device__ float g_part[BATCH][GBLK][NCH * NCH];   // per-block gram partials
__device__ float g_psum[BATCH][GBLK][NCH];         // per-block channel-sum partials
__device__ float g_mean[BATCH][NCH];
__device__ float g_half[BATCH][NCH * NCH];         // cov^{1/2}
__device__ float g_invh[BATCH][NCH * NCH];         // cov^{-1/2}
__device__ float g_At  [BATCH][NCH * NCH];         // A^T: g_At[k*64+c] = A[c][k]
__device__ float g_bias[BATCH][NCH];

// ---- packed f32x2 helpers ----
__device__ __forceinline__ void ffma2(unsigned long long& d,
                                      unsigned long long a,
                                      unsigned long long b) {
    asm("fma.rn.f32x2 %0, %1, %2, %0;" : "+l"(d) : "l"(a), "l"(b));
}
__device__ __forceinline__ unsigned long long fadd2(unsigned long long a,
                                                    unsigned long long b) {
    unsigned long long r;
    asm("add.rn.f32x2 %0, %1, %2;" : "=l"(r) : "l"(a), "l"(b));
    return r;
}
__device__ __forceinline__ unsigned long long dup2f(float v) {
    unsigned long long r;
    unsigned u = __float_as_uint(v);
    asm("mov.b64 %0, {%1, %1};" : "=l"(r) : "r"(u));
    return r;
}
__device__ __forceinline__ float lo32(unsigned long long v) {
    return __uint_as_float((unsigned)v);
}
__device__ __forceinline__ float hi32(unsigned long long v) {
    return __uint_as_float((unsigned)(v >> 32));
}

// ---- cp.async helpers ----
__device__ __forceinline__ void cp16(uint32_t smem_dst, const void* gsrc) {
    asm volatile("cp.async.ca.shared.global [%0], [%1], 16;\n"
                 :: "r"(smem_dst), "l"(gsrc));
}
__device__ __forceinline__ void cp_commit() {
    asm volatile("cp.async.commit_group;\n" ::: "memory");
}
template <int N>
__device__ __forceinline__ void cp_wait() {
    asm volatile("cp.async.wait_group %0;\n" :: "n"(N) : "memory");
}
__device__ __forceinline__ uint32_t smem_u32(const void* p) {
    return (uint32_t)__cvta_generic_to_shared(p);
}

// ============================================================================
// Kernel 1: Gram + channel sums. grid (GBLK, BATCH), 288 threads, 2 blocks/SM.
// Symmetry: 36 upper 8x8 tiles (8 pixel-groups x 36 threads), mirrored.
// Register-prefetch double-buffered 64-pixel tiles (R7 structure).
// ============================================================================
__global__ void __launch_bounds__(GT, 2) gram_kernel(const float* __restrict__ x) {
    __shared__ float tile[2][64 * NCH];            // 2 x 16 KB ping-pong
    __shared__ float red[GT];
    __shared__ unsigned long long ssum2[64];

    const int b   = blockIdx.y;
    const int blk = blockIdx.x;
    const int tid = threadIdx.x;
    const int g   = tid / 36;          // pixel-interleave group 0..7
    const int u   = tid - g * 36;      // upper-triangle tile index 0..35

    // (ti, tj) with ti <= tj from triangle index u
    int r = u, ti = 0;
    while (r >= 8 - ti) { r -= 8 - ti; ++ti; }
    const int tj = ti + r;

    unsigned long long acc2[8][4];
#pragma unroll
    for (int i = 0; i < 8; i++)
#pragma unroll
        for (int j = 0; j < 4; j++) acc2[i][j] = 0ull;

    unsigned long long sum2 = 0ull;
    const int cp = tid & 31, ph = tid >> 5;

    const float4* x4 = reinterpret_cast<const float4*>(x) +
                       ((size_t)b * HW + (size_t)blk * GPIX) * (NCH / 4);

    // preload tile 0
    float4 pf[4];
#pragma unroll
    for (int rr = 0; rr < 4; ++rr) {
        int f = tid + GT * rr;
        if (f < 1024) pf[rr] = x4[f];
    }
    {
        float4* t4 = reinterpret_cast<float4*>(tile[0]);
#pragma unroll
        for (int rr = 0; rr < 4; ++rr) {
            int f = tid + GT * rr;
            if (f < 1024) t4[f] = pf[rr];
        }
    }
    __syncthreads();

    for (int t = 0; t < GPIX / 64; ++t) {
        const int cb = t & 1;
        // issue prefetch of next tile (latency hidden by compute below)
        if (t + 1 < GPIX / 64) {
#pragma unroll
            for (int rr = 0; rr < 4; ++rr) {
                int f = tid + GT * rr;
                if (f < 1024) pf[rr] = x4[(size_t)(t + 1) * 1024 + f];
            }
        }

        const float4*     t4c = reinterpret_cast<const float4*>(tile[cb]);
        const ulonglong2* tb2 = reinterpret_cast<const ulonglong2*>(tile[cb]);

#pragma unroll 4
        for (int p = g; p < 64; p += 8) {
            const float4 a0 = t4c[p * 16 + 2 * ti];
            const float4 a1 = t4c[p * 16 + 2 * ti + 1];
            const ulonglong2 b0 = tb2[p * 16 + 2 * tj];
            const ulonglong2 b1 = tb2[p * 16 + 2 * tj + 1];
            float av[8] = {a0.x, a0.y, a0.z, a0.w, a1.x, a1.y, a1.z, a1.w};
            unsigned long long bp[4] = {b0.x, b0.y, b1.x, b1.y};
#pragma unroll
            for (int i = 0; i < 8; i++) {
                unsigned long long ad = dup2f(av[i]);
#pragma unroll
                for (int j = 0; j < 4; j++) ffma2(acc2[i][j], ad, bp[j]);
            }
        }

        if (tid < 64) {
            const unsigned long long* tp =
                reinterpret_cast<const unsigned long long*>(tile[cb]);
#pragma unroll 8
            for (int p = ph; p < 64; p += 2)
                sum2 = fadd2(sum2, tp[p * 32 + cp]);
        }
        __syncthreads();

        if (t + 1 < GPIX / 64) {
            float4* t4n = reinterpret_cast<float4*>(tile[cb ^ 1]);
#pragma unroll
            for (int rr = 0; rr < 4; ++rr) {
                int f = tid + GT * rr;
                if (f < 1024) t4n[f] = pf[rr];
            }
            __syncthreads();
        }
    }

    // channel sums: combine the two pixel-halves
    if (tid < 64) ssum2[tid] = sum2;
    __syncthreads();
    if (tid < 32) {
        unsigned long long v = fadd2(ssum2[tid], ssum2[tid + 32]);
        g_psum[b][blk][2 * tid]     = lo32(v);
        g_psum[b][blk][2 * tid + 1] = hi32(v);
    }
    __syncthreads();

    // reduce acc over 8 pixel-groups; write tile and its mirror
#pragma unroll 1
    for (int e = 0; e < 64; ++e) {
        const int ii = e >> 3, jj = e & 7;
        const unsigned long long v2 = acc2[ii][jj >> 1];
        red[g * 36 + u] = (jj & 1) ? hi32(v2) : lo32(v2);
        __syncthreads();
        if (tid < 36) {
            float v = 0.f;
#pragma unroll
            for (int gg = 0; gg < 8; ++gg) v += red[gg * 36 + tid];
            const int row = 8 * ti + ii;
            const int col = 8 * tj + jj;
            g_part[b][blk][row * NCH + col] = v;
            g_part[b][blk][col * NCH + row] = v;   // symmetry (diag: same value)
        }
        __syncthreads();
    }
}

// ============================================================================
// 64x64 smem matmul helpers (stride MS), packed f32x2.
// ============================================================================
__device__ __forceinline__ void mm64p(const float* __restrict__ A,
                                      const float* __restrict__ B,
                                      unsigned long long r2[8], int i, int j0) {
#pragma unroll
    for (int q = 0; q < 8; q++) r2[q] = 0ull;
#pragma unroll 8
    for (int k = 0; k < 64; ++k) {
        unsigned long long ad = dup2f(A[i * MS + k]);
        const ulonglong2* b2 = reinterpret_cast<const ulonglong2*>(B + k * MS + j0);
        ulonglong2 x0 = b2[0], x1 = b2[1], x2 = b2[2], x3 = b2[3];
        ffma2(r2[0], ad, x0.x); ffma2(r2[1], ad, x0.y);
        ffma2(r2[2], ad, x1.x); ffma2(r2[3], ad, x1.y);
        ffma2(r2[4], ad, x2.x); ffma2(r2[5], ad, x2.y);
        ffma2(r2[6], ad, x3.x); ffma2(r2[7], ad, x3.y);
    }
}

__device__ __forceinline__ void mm64p8(const float* __restrict__ A,
                                       const float* __restrict__ B,
                                       unsigned long long r2[4], int i, int j0) {
#pragma unroll
    for (int q = 0; q < 4; q++) r2[q] = 0ull;
#pragma unroll 8
    for (int k = 0; k < 64; ++k) {
        unsigned long long ad = dup2f(A[i * MS + k]);
        const ulonglong2* b2 = reinterpret_cast<const ulonglong2*>(B + k * MS + j0);
        ulonglong2 x0 = b2[0], x1 = b2[1];
        ffma2(r2[0], ad, x0.x); ffma2(r2[1], ad, x0.y);
        ffma2(r2[2], ad, x1.x); ffma2(r2[3], ad, x1.y);
    }
}

// ============================================================================
// Kernel 2: fused cov-reduction + Newton-Schulz. grid BATCH, 512 threads.
// ============================================================================
__global__ void __launch_bounds__(512) ns_kernel() {
    extern __shared__ float dsm[];
    float* sY = dsm;
    float* sZ = sY + 64 * MS;
    float* sT = sZ + 64 * MS;
    __shared__ float mean_s[NCH];

    const int b = blockIdx.x, tid = threadIdx.x;
    const int i8  = tid >> 3, j8 = (tid & 7) * 8;            // T-phase mapping
    const int u   = tid & 255;
    const int i16 = u >> 2, j16 = (u & 3) * 16;              // half-phase mapping

    if (tid < NCH) {
        float s = 0.f;
#pragma unroll
        for (int k = 0; k < GBLK; ++k) s += g_psum[b][k][tid];
        float m = s * (1.f / (float)HW);
        mean_s[tid] = m;
        g_mean[b][tid] = m;
    }
    __syncthreads();

    const float inv_d = 1.f / (float)(HW - 1);
    for (int e = tid; e < 4096; e += 512) {
        float s = 0.f;
#pragma unroll
        for (int k = 0; k < GBLK; ++k) s += g_part[b][k][e];
        int i = e >> 6, j = e & 63;
        sZ[i * MS + j] = (s - (float)HW * mean_s[i] * mean_s[j]) * inv_d;
    }
    __syncthreads();

    if (tid < 64) {
        float s = 0.f;
        for (int j = 0; j < 64; ++j) s += fabsf(sZ[tid * MS + j]);
        sY[tid] = s;
    }
    __syncthreads();
    if (tid == 0) {
        float m = 0.f;
        for (int r = 0; r < 64; ++r) m = fmaxf(m, sY[r]);
        sT[0] = m;
    }
    __syncthreads();
    const float c = sT[0];
    const float inv_c = 1.f / c;
    __syncthreads();

    for (int e = tid; e < 4096; e += 512) {
        int r = e >> 6, q = e & 63;
        float v = sZ[r * MS + q];
        sY[r * MS + q] = v * inv_c;
        sZ[r * MS + q] = (r == q) ? 1.f : 0.f;
    }
    __syncthreads();

    for (int it = 0; it < NS_ITERS; ++it) {
        unsigned long long t2[4];
        mm64p8(sZ, sY, t2, i8, j8);
#pragma unroll
        for (int q = 0; q < 4; q++) {
            int j = j8 + 2 * q;
            sT[i8 * MS + j]     = ((i8 == j)     ? 1.5f : 0.f) - 0.5f * lo32(t2[q]);
            sT[i8 * MS + j + 1] = ((i8 == j + 1) ? 1.5f : 0.f) - 0.5f * hi32(t2[q]);
        }
        __syncthreads();

        unsigned long long r2[8];
        if (tid < 256) mm64p(sY, sT, r2, i16, j16);
        else           mm64p(sT, sZ, r2, i16, j16);
        __syncthreads();
        float* dst = (tid < 256) ? sY : sZ;
#pragma unroll
        for (int q = 0; q < 8; q++) {
            dst[i16 * MS + j16 + 2 * q]     = lo32(r2[q]);
            dst[i16 * MS + j16 + 2 * q + 1] = hi32(r2[q]);
        }
        __syncthreads();
    }

    const float sc = sqrtf(c), isc = rsqrtf(c);
    for (int e = tid; e < 4096; e += 512) {
        int r = e >> 6, q = e & 63;
        g_half[b][e] = sY[r * MS + q] * sc;
        g_invh[b][e] = sZ[r * MS + q] * isc;
    }
}

// ============================================================================
// Kernel 3: A_b = alpha I + (1-alpha) * half[perm[b]] * invh[b] (stored A^T),
//           bias_b = (1-alpha)*(mean[perm[b]] - M*mean[b]). grid BATCH, 512.
// ============================================================================
__global__ void __launch_bounds__(512) comb_kernel(const int* __restrict__ perm,
                                                   const float* __restrict__ alpha) {
    __shared__ float sS[64 * MS], sTi[64 * MS], red[512];
    const int b = blockIdx.x, tid = threadIdx.x;
    const int pb = perm[b];
    const float al = alpha[b];
    const float oma = 1.f - al;

    for (int e = tid; e < 4096; e += 512) {
        int r = e >> 6, q = e & 63;
        sS [r * MS + q] = g_half[pb][e];
        sTi[r * MS + q] = g_invh[b][e];
    }
    __syncthreads();

    const int i = tid >> 3, j0 = (tid & 7) * 8;
    unsigned long long m2[4];
    mm64p8(sS, sTi, m2, i, j0);   // M[i][j0..j0+7]

    float m[8];
#pragma unroll
    for (int q = 0; q < 4; q++) { m[2 * q] = lo32(m2[q]); m[2 * q + 1] = hi32(m2[q]); }

    float pdot = 0.f;
#pragma unroll
    for (int q = 0; q < 8; q++) {
        int j = j0 + q;
        g_At[b][j * 64 + i] = ((i == j) ? al : 0.f) + oma * m[q];  // A^T[j][i]=A[i][j]
        pdot += m[q] * g_mean[b][j];
    }
    red[tid] = pdot;
    __syncthreads();
    if (tid < 64) {
        float dot = 0.f;
#pragma unroll
        for (int t = 0; t < 8; t++) dot += red[tid * 8 + t];
        g_bias[b][tid] = oma * (g_mean[pb][tid] - dot);
    }
}

// ============================================================================
// Kernel 4: out[p] = A*x[p] + bias. grid (ABLK, BATCH), 512 threads, 1 blk/SM.
// 512-pixel tile, thread = 8px x 8ch (B/FMA = 1.0). Two 4-px phases per tile;
// cp.async stages next tile's half into the half just released (no dbl buffer).
// Dynamic smem: 512*XS + 4096 + 64 floats (~152 KB).
// ============================================================================
__global__ void __launch_bounds__(512) apply_kernel(const float* __restrict__ x,
                                                    float* __restrict__ out) {
    extern __shared__ float dsm[];
    float* sx = dsm;                 // 512 * XS
    float* sA = sx + AT * XS;        // 64*64 (A^T, row k contiguous in c)
    float* sb = sA + 4096;           // 64

    const int b = blockIdx.y, blk = blockIdx.x, tid = threadIdx.x;

    for (int e = tid; e < 4096; e += 512) sA[e] = g_At[b][e];
    if (tid < 64) sb[tid] = g_bias[b][tid];
    // sA/sb visibility guaranteed by the first cp_wait + __syncthreads below.

    const int ci = tid & 7;          // channel group: c0 = 8*ci
    const int pi = tid >> 3;         // pixel slot 0..63 ; pixels pi + 64*s
    const int c0 = ci * 8;

    const float4* x4 = reinterpret_cast<const float4*>(x) +
                       ((size_t)b * HW + (size_t)blk * APIX) * (NCH / 4);
    float4* o4 = reinterpret_cast<float4*>(out) +
                 ((size_t)b * HW + (size_t)blk * APIX) * (NCH / 4);
    const float4* sxv = reinterpret_cast<const float4*>(sx);
    const ulonglong2* sA2 = reinterpret_cast<const ulonglong2*>(sA);
    const unsigned long long* sb2 =
        reinterpret_cast<const unsigned long long*>(sb + c0);
    const uint32_t sxa = smem_u32(sx);

    // stage half h (256 px = 4096 float4, 8 per thread) of tile t; one group.
#define STAGE_HALF(t, h)                                                     \
    do {                                                                     \
        _Pragma("unroll")                                                    \
        for (int rr = 0; rr < 8; ++rr) {                                     \
            int f = (h) * 4096 + tid + 512 * rr;                             \
            int p = f >> 4, q = f & 15;                                      \
            cp16(sxa + (p * XS + q * 4) * 4, x4 + (size_t)(t) * 8192 + f);   \
        }                                                                    \
        cp_commit();                                                         \
    } while (0)

    // compute 4 pixels (s = s0..s0+3) against full K, write results.
#define COMPUTE_PHASE(t, s0)                                                 \
    do {                                                                     \
        unsigned long long acc2[4][4];                                       \
        _Pragma("unroll")                                                    \
        for (int s = 0; s < 4; s++)                                          \
            _Pragma("unroll")                                                \
            for (int j = 0; j < 4; j++) acc2[s][j] = sb2[j];                 \
        _Pragma("unroll 4")                                                  \
        for (int k4 = 0; k4 < 16; ++k4) {                                    \
            ulonglong2 ap[4], aq[4];                                         \
            _Pragma("unroll")                                                \
            for (int kk = 0; kk < 4; ++kk) {                                 \
                ap[kk] = sA2[(4 * k4 + kk) * 16 + 2 * ci];                   \
                aq[kk] = sA2[(4 * k4 + kk) * 16 + 2 * ci + 1];               \
            }                                                                \
            _Pragma("unroll")                                                \
            for (int s = 0; s < 4; s++) {                                    \
                const int p = pi + 64 * ((s0) + s);                          \
                const float4 xv = sxv[p * (XS / 4) + k4];                    \
                float xk[4] = {xv.x, xv.y, xv.z, xv.w};                      \
                _Pragma("unroll")                                            \
                for (int kk = 0; kk < 4; ++kk) {                             \
                    unsigned long long xd = dup2f(xk[kk]);                   \
                    ffma2(acc2[s][0], xd, ap[kk].x);                         \
                    ffma2(acc2[s][1], xd, ap[kk].y);                         \
                    ffma2(acc2[s][2], xd, aq[kk].x);                         \
                    ffma2(acc2[s][3], xd, aq[kk].y);                         \
                }                                                            \
            }                                                                \
        }                                                                    \
        _Pragma("unroll")                                                    \
        for (int s = 0; s < 4; s++) {                                        \
            const int p = pi + 64 * ((s0) + s);                              \
            o4[(size_t)(t) * 8192 + p * 16 + 2 * ci] =                       \
                make_float4(lo32(acc2[s][0]), hi32(acc2[s][0]),              \
                            lo32(acc2[s][1]), hi32(acc2[s][1]));             \
            o4[(size_t)(t) * 8192 + p * 16 + 2 * ci + 1] =                   \
                make_float4(lo32(acc2[s][2]), hi32(acc2[s][2]),              \
                            lo32(acc2[s][3]), hi32(acc2[s][3]));             \
        }                                                                    \
    } while (0)

    STAGE_HALF(0, 0);
    STAGE_HALF(0, 1);

    const int NT = APIX / AT;        // 8 tiles
    for (int t = 0; t < NT; ++t) {
        // Phase 1: needs (t,h1); the newest pending group may lag.
        cp_wait<1>();
        __syncthreads();
        COMPUTE_PHASE(t, 0);
        __syncthreads();             // all reads of h1 done
        if (t + 1 < NT) STAGE_HALF(t + 1, 0);

        // Phase 2: needs (t,h2) = second-newest if we just committed, else newest.
        if (t + 1 < NT) cp_wait<1>(); else cp_wait<0>();
        __syncthreads();
        COMPUTE_PHASE(t, 4);
        __syncthreads();             // all reads of h2 done
        if (t + 1 < NT) STAGE_HALF(t + 1, 1);
    }
#undef STAGE_HALF
#undef COMPUTE_PHASE
}

// ============================================================================
extern "C" void kernel_launch(void* const* d_in, const int* in_sizes, int n_in,
                              void* d_out, int out_size) {
    (void)in_sizes; (void)n_in; (void)out_size;
    const float* x     = (const float*)d_in[0];
    const int*   perm  = (const int*)d_in[1];
    const float* alpha = (const float*)d_in[2];
    float*       out   = (float*)d_out;

    const int ns_smem    = 3 * 64 * MS * (int)sizeof(float);               // 52224 B
    const int apply_smem = (AT * XS + 4096 + 64) * (int)sizeof(float);     // 155904 B
    cudaFuncSetAttribute(ns_kernel, cudaFuncAttributeMaxDynamicSharedMemorySize, ns_smem);
    cudaFuncSetAttribute(apply_kernel, cudaFuncAttributeMaxDynamicSharedMemorySize, apply_smem);

    gram_kernel<<<dim3(GBLK, BATCH), GT>>>(x);
    ns_kernel<<<BATCH, 512, ns_smem>>>();
    comb_kernel<<<BATCH, 512>>>(perm, alpha);
    apply_kernel<<<dim3(ABLK, BATCH), 512, apply_smem>>>(x, out);
}

// round 12
// speedup vs baseline: 1.6222x; 1.6222x over previous
#include <cuda_runtime.h>
#include <cuda_bf16.h>
#include <cstdint>

// WCT: out[b] = alpha*x[b] + (1-alpha)*( M_b * (x[b]-mean_b) + mean_{perm[b]} )
// M_b = cov_{perm[b]}^{1/2} * cov_b^{-1/2}, roots via coupled Newton-Schulz.
// Folded: out = A_b * x + bias_b with A_b = alpha*I + (1-alpha)*M_b.
// R11: apply on warp-level mma.sync (bf16 2-way split, sm_80 PTX -> HMMA).
//      gram/ns/comb = exact 649us configuration.

#define BATCH 16
#define HW 65536
#define NCH 64
#define GBLK 16
#define GPIX (HW / GBLK)
#define NS_ITERS 6
#define MS 68
#define GT 288

// apply config
#define ABLKS 16                // apply blocks per batch
#define APB   4096              // pixels per apply block
#define ATL   128               // pixels per tile
#define NTIL  (APB / ATL)       // 32 tiles
#define XROW  72                // padded bf16 row stride (conflict-free ldmatrix)
#define AROW  72

// ---- device scratch ----
__device__ float g_part[BATCH][GBLK][NCH * NCH];
__device__ float g_psum[BATCH][GBLK][NCH];
__device__ float g_mean[BATCH][NCH];
__device__ float g_half[BATCH][NCH * NCH];
__device__ float g_invh[BATCH][NCH * NCH];
__device__ float g_A  [BATCH][NCH * NCH];          // row-major: g_A[c*64+k]
__device__ float g_bias[BATCH][NCH];

// ---- packed f32x2 helpers ----
__device__ __forceinline__ void ffma2(unsigned long long& d,
                                      unsigned long long a,
                                      unsigned long long b) {
    asm("fma.rn.f32x2 %0, %1, %2, %0;" : "+l"(d) : "l"(a), "l"(b));
}
__device__ __forceinline__ unsigned long long fadd2(unsigned long long a,
                                                    unsigned long long b) {
    unsigned long long r;
    asm("add.rn.f32x2 %0, %1, %2;" : "=l"(r) : "l"(a), "l"(b));
    return r;
}
__device__ __forceinline__ unsigned long long dup2f(float v) {
    unsigned long long r;
    unsigned u = __float_as_uint(v);
    asm("mov.b64 %0, {%1, %1};" : "=l"(r) : "r"(u));
    return r;
}
__device__ __forceinline__ float lo32(unsigned long long v) {
    return __uint_as_float((unsigned)v);
}
__device__ __forceinline__ float hi32(unsigned long long v) {
    return __uint_as_float((unsigned)(v >> 32));
}

// ---- warp mma helpers (sm_80-compatible PTX; no 'a' features) ----
__device__ __forceinline__ uint32_t smem_u32(const void* p) {
    return (uint32_t)__cvta_generic_to_shared(p);
}
__device__ __forceinline__ void ldm4(uint32_t r[4], uint32_t addr) {
    asm volatile("ldmatrix.sync.aligned.m8n8.x4.shared.b16 {%0,%1,%2,%3}, [%4];"
                 : "=r"(r[0]), "=r"(r[1]), "=r"(r[2]), "=r"(r[3]) : "r"(addr));
}
__device__ __forceinline__ void mma_bf16(float c[4], const uint32_t a[4],
                                         const uint32_t b0, const uint32_t b1) {
    asm volatile(
        "mma.sync.aligned.m16n8k16.row.col.f32.bf16.bf16.f32 "
        "{%0,%1,%2,%3}, {%4,%5,%6,%7}, {%8,%9}, {%0,%1,%2,%3};"
        : "+f"(c[0]), "+f"(c[1]), "+f"(c[2]), "+f"(c[3])
        : "r"(a[0]), "r"(a[1]), "r"(a[2]), "r"(a[3]), "r"(b0), "r"(b1));
}
__device__ __forceinline__ unsigned short bfh(float v) {
    return __bfloat16_as_ushort(__float2bfloat16_rn(v));
}

// ============================================================================
// Kernel 1: Gram + channel sums (exact 649us version). grid (GBLK,BATCH), 288.
// ============================================================================
__global__ void __launch_bounds__(GT) gram_kernel(const float* __restrict__ x) {
    __shared__ float tile[2][64 * NCH];
    __shared__ float red[GT];
    __shared__ unsigned long long ssum2[64];

    const int b   = blockIdx.y;
    const int blk = blockIdx.x;
    const int tid = threadIdx.x;
    const int g   = tid / 36;
    const int u   = tid - g * 36;

    int r = u, ti = 0;
    while (r >= 8 - ti) { r -= 8 - ti; ++ti; }
    const int tj = ti + r;

    unsigned long long acc2[8][4];
#pragma unroll
    for (int i = 0; i < 8; i++)
#pragma unroll
        for (int j = 0; j < 4; j++) acc2[i][j] = 0ull;

    unsigned long long sum2 = 0ull;
    const int cp = tid & 31, ph = tid >> 5;

    const float4* x4 = reinterpret_cast<const float4*>(x) +
                       ((size_t)b * HW + (size_t)blk * GPIX) * (NCH / 4);

    float4 pf[4];
#pragma unroll
    for (int rr = 0; rr < 4; ++rr) {
        int f = tid + GT * rr;
        if (f < 1024) pf[rr] = x4[f];
    }
    {
        float4* t4 = reinterpret_cast<float4*>(tile[0]);
#pragma unroll
        for (int rr = 0; rr < 4; ++rr) {
            int f = tid + GT * rr;
            if (f < 1024) t4[f] = pf[rr];
        }
    }
    __syncthreads();

    for (int t = 0; t < GPIX / 64; ++t) {
        const int cb = t & 1;
        if (t + 1 < GPIX / 64) {
#pragma unroll
            for (int rr = 0; rr < 4; ++rr) {
                int f = tid + GT * rr;
                if (f < 1024) pf[rr] = x4[(size_t)(t + 1) * 1024 + f];
            }
        }

        const float4*     t4c = reinterpret_cast<const float4*>(tile[cb]);
        const ulonglong2* tb2 = reinterpret_cast<const ulonglong2*>(tile[cb]);

#pragma unroll 4
        for (int p = g; p < 64; p += 8) {
            const float4 a0 = t4c[p * 16 + 2 * ti];
            const float4 a1 = t4c[p * 16 + 2 * ti + 1];
            const ulonglong2 b0 = tb2[p * 16 + 2 * tj];
            const ulonglong2 b1 = tb2[p * 16 + 2 * tj + 1];
            float av[8] = {a0.x, a0.y, a0.z, a0.w, a1.x, a1.y, a1.z, a1.w};
            unsigned long long bp[4] = {b0.x, b0.y, b1.x, b1.y};
#pragma unroll
            for (int i = 0; i < 8; i++) {
                unsigned long long ad = dup2f(av[i]);
#pragma unroll
                for (int j = 0; j < 4; j++) ffma2(acc2[i][j], ad, bp[j]);
            }
        }

        if (tid < 64) {
            const unsigned long long* tp =
                reinterpret_cast<const unsigned long long*>(tile[cb]);
#pragma unroll 8
            for (int p = ph; p < 64; p += 2)
                sum2 = fadd2(sum2, tp[p * 32 + cp]);
        }
        __syncthreads();

        if (t + 1 < GPIX / 64) {
            float4* t4n = reinterpret_cast<float4*>(tile[cb ^ 1]);
#pragma unroll
            for (int rr = 0; rr < 4; ++rr) {
                int f = tid + GT * rr;
                if (f < 1024) t4n[f] = pf[rr];
            }
            __syncthreads();
        }
    }

    if (tid < 64) ssum2[tid] = sum2;
    __syncthreads();
    if (tid < 32) {
        unsigned long long v = fadd2(ssum2[tid], ssum2[tid + 32]);
        g_psum[b][blk][2 * tid]     = lo32(v);
        g_psum[b][blk][2 * tid + 1] = hi32(v);
    }
    __syncthreads();

#pragma unroll 1
    for (int e = 0; e < 64; ++e) {
        const int ii = e >> 3, jj = e & 7;
        const unsigned long long v2 = acc2[ii][jj >> 1];
        red[g * 36 + u] = (jj & 1) ? hi32(v2) : lo32(v2);
        __syncthreads();
        if (tid < 36) {
            float v = 0.f;
#pragma unroll
            for (int gg = 0; gg < 8; ++gg) v += red[gg * 36 + tid];
            const int row = 8 * ti + ii;
            const int col = 8 * tj + jj;
            g_part[b][blk][row * NCH + col] = v;
            g_part[b][blk][col * NCH + row] = v;
        }
        __syncthreads();
    }
}

// ============================================================================
// 64x64 smem matmul helpers (stride MS), packed f32x2.
// ============================================================================
__device__ __forceinline__ void mm64p(const float* __restrict__ A,
                                      const float* __restrict__ B,
                                      unsigned long long r2[8], int i, int j0) {
#pragma unroll
    for (int q = 0; q < 8; q++) r2[q] = 0ull;
#pragma unroll 8
    for (int k = 0; k < 64; ++k) {
        unsigned long long ad = dup2f(A[i * MS + k]);
        const ulonglong2* b2 = reinterpret_cast<const ulonglong2*>(B + k * MS + j0);
        ulonglong2 x0 = b2[0], x1 = b2[1], x2 = b2[2], x3 = b2[3];
        ffma2(r2[0], ad, x0.x); ffma2(r2[1], ad, x0.y);
        ffma2(r2[2], ad, x1.x); ffma2(r2[3], ad, x1.y);
        ffma2(r2[4], ad, x2.x); ffma2(r2[5], ad, x2.y);
        ffma2(r2[6], ad, x3.x); ffma2(r2[7], ad, x3.y);
    }
}

__device__ __forceinline__ void mm64p8(const float* __restrict__ A,
                                       const float* __restrict__ B,
                                       unsigned long long r2[4], int i, int j0) {
#pragma unroll
    for (int q = 0; q < 4; q++) r2[q] = 0ull;
#pragma unroll 8
    for (int k = 0; k < 64; ++k) {
        unsigned long long ad = dup2f(A[i * MS + k]);
        const ulonglong2* b2 = reinterpret_cast<const ulonglong2*>(B + k * MS + j0);
        ulonglong2 x0 = b2[0], x1 = b2[1];
        ffma2(r2[0], ad, x0.x); ffma2(r2[1], ad, x0.y);
        ffma2(r2[2], ad, x1.x); ffma2(r2[3], ad, x1.y);
    }
}

// ============================================================================
// Kernel 2: fused cov-reduction + Newton-Schulz. grid BATCH, 512 threads.
// ============================================================================
__global__ void __launch_bounds__(512) ns_kernel() {
    extern __shared__ float dsm[];
    float* sY = dsm;
    float* sZ = sY + 64 * MS;
    float* sT = sZ + 64 * MS;
    __shared__ float mean_s[NCH];

    const int b = blockIdx.x, tid = threadIdx.x;
    const int i8  = tid >> 3, j8 = (tid & 7) * 8;
    const int u   = tid & 255;
    const int i16 = u >> 2, j16 = (u & 3) * 16;

    if (tid < NCH) {
        float s = 0.f;
#pragma unroll
        for (int k = 0; k < GBLK; ++k) s += g_psum[b][k][tid];
        float m = s * (1.f / (float)HW);
        mean_s[tid] = m;
        g_mean[b][tid] = m;
    }
    __syncthreads();

    const float inv_d = 1.f / (float)(HW - 1);
    for (int e = tid; e < 4096; e += 512) {
        float s = 0.f;
#pragma unroll
        for (int k = 0; k < GBLK; ++k) s += g_part[b][k][e];
        int i = e >> 6, j = e & 63;
        sZ[i * MS + j] = (s - (float)HW * mean_s[i] * mean_s[j]) * inv_d;
    }
    __syncthreads();

    if (tid < 64) {
        float s = 0.f;
        for (int j = 0; j < 64; ++j) s += fabsf(sZ[tid * MS + j]);
        sY[tid] = s;
    }
    __syncthreads();
    if (tid == 0) {
        float m = 0.f;
        for (int r = 0; r < 64; ++r) m = fmaxf(m, sY[r]);
        sT[0] = m;
    }
    __syncthreads();
    const float c = sT[0];
    const float inv_c = 1.f / c;
    __syncthreads();

    for (int e = tid; e < 4096; e += 512) {
        int r = e >> 6, q = e & 63;
        float v = sZ[r * MS + q];
        sY[r * MS + q] = v * inv_c;
        sZ[r * MS + q] = (r == q) ? 1.f : 0.f;
    }
    __syncthreads();

    for (int it = 0; it < NS_ITERS; ++it) {
        unsigned long long t2[4];
        mm64p8(sZ, sY, t2, i8, j8);
#pragma unroll
        for (int q = 0; q < 4; q++) {
            int j = j8 + 2 * q;
            sT[i8 * MS + j]     = ((i8 == j)     ? 1.5f : 0.f) - 0.5f * lo32(t2[q]);
            sT[i8 * MS + j + 1] = ((i8 == j + 1) ? 1.5f : 0.f) - 0.5f * hi32(t2[q]);
        }
        __syncthreads();

        unsigned long long r2[8];
        if (tid < 256) mm64p(sY, sT, r2, i16, j16);
        else           mm64p(sT, sZ, r2, i16, j16);
        __syncthreads();
        float* dst = (tid < 256) ? sY : sZ;
#pragma unroll
        for (int q = 0; q < 8; q++) {
            dst[i16 * MS + j16 + 2 * q]     = lo32(r2[q]);
            dst[i16 * MS + j16 + 2 * q + 1] = hi32(r2[q]);
        }
        __syncthreads();
    }

    const float sc = sqrtf(c), isc = rsqrtf(c);
    for (int e = tid; e < 4096; e += 512) {
        int r = e >> 6, q = e & 63;
        g_half[b][e] = sY[r * MS + q] * sc;
        g_invh[b][e] = sZ[r * MS + q] * isc;
    }
}

// ============================================================================
// Kernel 3: A_b (row-major) + bias_b. grid BATCH, 512 threads.
// ============================================================================
__global__ void __launch_bounds__(512) comb_kernel(const int* __restrict__ perm,
                                                   const float* __restrict__ alpha) {
    __shared__ float sS[64 * MS], sTi[64 * MS], red[512];
    const int b = blockIdx.x, tid = threadIdx.x;
    const int pb = perm[b];
    const float al = alpha[b];
    const float oma = 1.f - al;

    for (int e = tid; e < 4096; e += 512) {
        int r = e >> 6, q = e & 63;
        sS [r * MS + q] = g_half[pb][e];
        sTi[r * MS + q] = g_invh[b][e];
    }
    __syncthreads();

    const int i = tid >> 3, j0 = (tid & 7) * 8;
    unsigned long long m2[4];
    mm64p8(sS, sTi, m2, i, j0);

    float m[8];
#pragma unroll
    for (int q = 0; q < 4; q++) { m[2 * q] = lo32(m2[q]); m[2 * q + 1] = hi32(m2[q]); }

    float pdot = 0.f;
#pragma unroll
    for (int q = 0; q < 8; q++) {
        int j = j0 + q;
        g_A[b][i * 64 + j] = ((i == j) ? al : 0.f) + oma * m[q];
        pdot += m[q] * g_mean[b][j];
    }
    red[tid] = pdot;
    __syncthreads();
    if (tid < 64) {
        float dot = 0.f;
#pragma unroll
        for (int t = 0; t < 8; t++) dot += red[tid * 8 + t];
        g_bias[b][tid] = oma * (g_mean[pb][tid] - dot);
    }
}

// ============================================================================
// Kernel 4: out = A*x + bias via mma.sync bf16 split. grid (ABLKS,BATCH), 256.
// Tile = 128 px. Warp (of 8) = 32px x 32ch: 2 m16 x 4 n8 x 4 k16 x 3 passes.
// X staged bf16 h|l, stride-72 rows (conflict-free ldmatrix), double-buffered.
// A's B-fragments hoisted to registers (Bh/Bl: 4 ksteps x 4 n8 x 2 regs each).
// Dynamic smem layout (bytes):
//   HX0 0 | HX1 18432 | LX0 36864 | LX1 55296 | AH 73728 | AL 82944 | BIAS 92160
// ============================================================================
#define SM_HX0  0
#define SM_HX1  18432
#define SM_LX0  36864
#define SM_LX1  55296
#define SM_AH   73728
#define SM_AL   82944
#define SM_BIAS 92160
#define APPLY_SMEM (SM_BIAS + 256)

__device__ __forceinline__ void stage_tile(unsigned short* hx, unsigned short* lx,
                                           const float4* __restrict__ src, int tid) {
#pragma unroll
    for (int r = 0; r < 8; ++r) {
        const int f = tid + 256 * r;          // 2048 float4 = 128 px x 16
        const float4 v = src[f];
        const int px = f >> 4, k0 = (f & 15) * 4;
        unsigned short h0 = bfh(v.x), h1 = bfh(v.y), h2 = bfh(v.z), h3 = bfh(v.w);
        float r0 = v.x - __bfloat162float(__ushort_as_bfloat16(h0));
        float r1 = v.y - __bfloat162float(__ushort_as_bfloat16(h1));
        float r2 = v.z - __bfloat162float(__ushort_as_bfloat16(h2));
        float r3 = v.w - __bfloat162float(__ushort_as_bfloat16(h3));
        uint2 hp, lp;
        hp.x = (uint32_t)h0 | ((uint32_t)h1 << 16);
        hp.y = (uint32_t)h2 | ((uint32_t)h3 << 16);
        lp.x = (uint32_t)bfh(r0) | ((uint32_t)bfh(r1) << 16);
        lp.y = (uint32_t)bfh(r2) | ((uint32_t)bfh(r3) << 16);
        *reinterpret_cast<uint2*>(hx + px * XROW + k0) = hp;
        *reinterpret_cast<uint2*>(lx + px * XROW + k0) = lp;
    }
}

__global__ void __launch_bounds__(256) apply_mma_kernel(const float* __restrict__ x,
                                                        float* __restrict__ out) {
    extern __shared__ char smem[];
    unsigned short* HX[2] = {(unsigned short*)(smem + SM_HX0),
                             (unsigned short*)(smem + SM_HX1)};
    unsigned short* LX[2] = {(unsigned short*)(smem + SM_LX0),
                             (unsigned short*)(smem + SM_LX1)};
    unsigned short* AH = (unsigned short*)(smem + SM_AH);
    unsigned short* AL = (unsigned short*)(smem + SM_AL);
    float* sbias = (float*)(smem + SM_BIAS);

    const int tid = threadIdx.x;
    const int w = tid >> 5, lane = tid & 31;
    const int b = blockIdx.y, blk = blockIdx.x;

    // ---- prologue: A -> bf16 split in smem; bias ----
    for (int e = tid; e < 4096; e += 256) {
        const int c = e >> 6, k = e & 63;
        const float a = g_A[b][e];
        unsigned short h = bfh(a);
        float rl = a - __bfloat162float(__ushort_as_bfloat16(h));
        AH[c * AROW + k] = h;
        AL[c * AROW + k] = bfh(rl);
    }
    if (tid < 64) sbias[tid] = g_bias[b][tid];

    const float4* x4 = reinterpret_cast<const float4*>(x) +
                       ((size_t)b * HW + (size_t)blk * APB) * (NCH / 4);
    float* ob = out + ((size_t)b * HW + (size_t)blk * APB) * NCH;

    stage_tile(HX[0], LX[0], x4, tid);
    __syncthreads();

    // ---- hoist B fragments (A matrix) into registers ----
    const int pxb   = (w >> 1) * 32;     // warp px base within tile
    const int nbase = (w & 1) * 32;      // warp channel base
    uint32_t Bh[4][4][2], Bl[4][4][2];
    {
        const uint32_t ah_s = smem_u32(AH), al_s = smem_u32(AL);
        const int rown = nbase + (lane & 7) + ((lane >> 4) << 3);
        const int koff = ((lane >> 3) & 1) * 8;
#pragma unroll
        for (int ks = 0; ks < 4; ++ks)
#pragma unroll
            for (int ntp = 0; ntp < 2; ++ntp) {
                const uint32_t off =
                    (uint32_t)(((rown + ntp * 16) * AROW + ks * 16 + koff) * 2);
                uint32_t rh[4], rl[4];
                ldm4(rh, ah_s + off);
                ldm4(rl, al_s + off);
                Bh[ks][ntp * 2][0] = rh[0]; Bh[ks][ntp * 2][1] = rh[1];
                Bh[ks][ntp * 2 + 1][0] = rh[2]; Bh[ks][ntp * 2 + 1][1] = rh[3];
                Bl[ks][ntp * 2][0] = rl[0]; Bl[ks][ntp * 2][1] = rl[1];
                Bl[ks][ntp * 2 + 1][0] = rl[2]; Bl[ks][ntp * 2 + 1][1] = rl[3];
            }
    }

    // bias pairs per thread (cols 2*(lane&3)+{0,1} of each n8 tile)
    float2 bv[4];
    {
        const int cpair = (lane & 3) * 2;
#pragma unroll
        for (int nt = 0; nt < 4; ++nt) {
            bv[nt].x = sbias[nbase + nt * 8 + cpair];
            bv[nt].y = sbias[nbase + nt * 8 + cpair + 1];
        }
    }

    // X ldmatrix per-lane offsets
    const int xrow = (lane & 15);
    const int xkof = ((lane >> 4) << 3);

    for (int t = 0; t < NTIL; ++t) {
        const int cb = t & 1;

        if (t + 1 < NTIL)
            stage_tile(HX[cb ^ 1], LX[cb ^ 1], x4 + (size_t)(t + 1) * 2048, tid);

        const uint32_t hx_s = smem_u32(HX[cb]), lx_s = smem_u32(LX[cb]);

        float C[2][4][4];
#pragma unroll
        for (int mt = 0; mt < 2; ++mt)
#pragma unroll
            for (int nt = 0; nt < 4; ++nt)
#pragma unroll
                for (int q = 0; q < 4; ++q) C[mt][nt][q] = 0.f;

#pragma unroll
        for (int ks = 0; ks < 4; ++ks) {
            uint32_t ah[2][4], al[2][4];
#pragma unroll
            for (int mt = 0; mt < 2; ++mt) {
                const uint32_t off = (uint32_t)(
                    ((pxb + mt * 16 + xrow) * XROW + ks * 16 + xkof) * 2);
                ldm4(ah[mt], hx_s + off);
                ldm4(al[mt], lx_s + off);
            }
#pragma unroll
            for (int mt = 0; mt < 2; ++mt)
#pragma unroll
                for (int nt = 0; nt < 4; ++nt) {
                    mma_bf16(C[mt][nt], ah[mt], Bh[ks][nt][0], Bh[ks][nt][1]);
                    mma_bf16(C[mt][nt], al[mt], Bh[ks][nt][0], Bh[ks][nt][1]);
                    mma_bf16(C[mt][nt], ah[mt], Bl[ks][nt][0], Bl[ks][nt][1]);
                }
        }

        // epilogue: bias add + store
        const int gr = lane >> 2, cpair = (lane & 3) * 2;
        const int pxg = t * ATL + pxb + gr;
#pragma unroll
        for (int mt = 0; mt < 2; ++mt) {
            float* row0 = ob + (size_t)(pxg + mt * 16) * NCH;
            float* row1 = row0 + 8 * NCH;
#pragma unroll
            for (int nt = 0; nt < 4; ++nt) {
                const int n = nbase + nt * 8 + cpair;
                *reinterpret_cast<float2*>(row0 + n) =
                    make_float2(C[mt][nt][0] + bv[nt].x, C[mt][nt][1] + bv[nt].y);
                *reinterpret_cast<float2*>(row1 + n) =
                    make_float2(C[mt][nt][2] + bv[nt].x, C[mt][nt][3] + bv[nt].y);
            }
        }
        __syncthreads();   // staging of t+1 done; buffers swap safely
    }
}

// ============================================================================
extern "C" void kernel_launch(void* const* d_in, const int* in_sizes, int n_in,
                              void* d_out, int out_size) {
    (void)in_sizes; (void)n_in; (void)out_size;
    const float* x     = (const float*)d_in[0];
    const int*   perm  = (const int*)d_in[1];
    const float* alpha = (const float*)d_in[2];
    float*       out   = (float*)d_out;

    const int ns_smem = 3 * 64 * MS * (int)sizeof(float);   // 52224 B
    cudaFuncSetAttribute(ns_kernel, cudaFuncAttributeMaxDynamicSharedMemorySize, ns_smem);
    cudaFuncSetAttribute(apply_mma_kernel, cudaFuncAttributeMaxDynamicSharedMemorySize,
                         APPLY_SMEM);

    gram_kernel<<<dim3(GBLK, BATCH), GT>>>(x);
    ns_kernel<<<BATCH, 512, ns_smem>>>();
    comb_kernel<<<BATCH, 512>>>(perm, alpha);
    apply_mma_kernel<<<dim3(ABLKS, BATCH), 256, APPLY_SMEM>>>(x, out);
}

// round 13
// speedup vs baseline: 2.0820x; 1.2835x over previous
#include <cuda_runtime.h>
#include <cuda_bf16.h>
#include <cstdint>

// WCT: out[b] = alpha*x[b] + (1-alpha)*( M_b * (x[b]-mean_b) + mean_{perm[b]} )
// M_b = cov_{perm[b]}^{1/2} * cov_b^{-1/2}, roots via coupled Newton-Schulz.
// Folded: out = A_b * x + bias_b with A_b = alpha*I + (1-alpha)*M_b.
// R12: gram also on mma.sync (h-only bf16: statistical cancellation over 64K
//      samples keeps cov error ~3e-6). ns/comb/apply = passing R11 versions.

#define BATCH 16
#define HW 65536
#define NCH 64
#define GBLK 16
#define GPIX (HW / GBLK)
#define NS_ITERS 6
#define MS 68

// apply config
#define ABLKS 16
#define APB   4096
#define ATL   128
#define NTIL  (APB / ATL)
#define XROW  72
#define AROW  72

// gram config
#define GXROW 72
#define GNT   (GPIX / 128)      // 32 staged tiles per block

// ---- device scratch ----
__device__ float g_part[BATCH][GBLK][NCH * NCH];
__device__ float g_psum[BATCH][GBLK][NCH];
__device__ float g_mean[BATCH][NCH];
__device__ float g_half[BATCH][NCH * NCH];
__device__ float g_invh[BATCH][NCH * NCH];
__device__ float g_A  [BATCH][NCH * NCH];          // row-major: g_A[c*64+k]
__device__ float g_bias[BATCH][NCH];

// ---- packed f32x2 helpers (ns/comb) ----
__device__ __forceinline__ void ffma2(unsigned long long& d,
                                      unsigned long long a,
                                      unsigned long long b) {
    asm("fma.rn.f32x2 %0, %1, %2, %0;" : "+l"(d) : "l"(a), "l"(b));
}
__device__ __forceinline__ unsigned long long dup2f(float v) {
    unsigned long long r;
    unsigned u = __float_as_uint(v);
    asm("mov.b64 %0, {%1, %1};" : "=l"(r) : "r"(u));
    return r;
}
__device__ __forceinline__ float lo32(unsigned long long v) {
    return __uint_as_float((unsigned)v);
}
__device__ __forceinline__ float hi32(unsigned long long v) {
    return __uint_as_float((unsigned)(v >> 32));
}

// ---- warp mma helpers ----
__device__ __forceinline__ uint32_t smem_u32(const void* p) {
    return (uint32_t)__cvta_generic_to_shared(p);
}
__device__ __forceinline__ void ldm4(uint32_t r[4], uint32_t addr) {
    asm volatile("ldmatrix.sync.aligned.m8n8.x4.shared.b16 {%0,%1,%2,%3}, [%4];"
                 : "=r"(r[0]), "=r"(r[1]), "=r"(r[2]), "=r"(r[3]) : "r"(addr));
}
__device__ __forceinline__ void ldm4t(uint32_t r[4], uint32_t addr) {
    asm volatile("ldmatrix.sync.aligned.m8n8.x4.trans.shared.b16 {%0,%1,%2,%3}, [%4];"
                 : "=r"(r[0]), "=r"(r[1]), "=r"(r[2]), "=r"(r[3]) : "r"(addr));
}
__device__ __forceinline__ void mma_bf16(float c[4], const uint32_t a[4],
                                         const uint32_t b0, const uint32_t b1) {
    asm volatile(
        "mma.sync.aligned.m16n8k16.row.col.f32.bf16.bf16.f32 "
        "{%0,%1,%2,%3}, {%4,%5,%6,%7}, {%8,%9}, {%0,%1,%2,%3};"
        : "+f"(c[0]), "+f"(c[1]), "+f"(c[2]), "+f"(c[3])
        : "r"(a[0]), "r"(a[1]), "r"(a[2]), "r"(a[3]), "r"(b0), "r"(b1));
}
__device__ __forceinline__ unsigned short bfh(float v) {
    return __bfloat16_as_ushort(__float2bfloat16_rn(v));
}

// upper-triangle m16n8 tile list: 20 tiles (mi 0..3, nj >= 2*mi)
__device__ __forceinline__ int gmi(int ti) {
    return (ti >= 8) + (ti >= 14) + (ti >= 18);
}
__device__ __forceinline__ int gnj(int ti) {
    int mi = gmi(ti);
    return ti - (mi >= 1) * 6 - (mi >= 2) * 4 - (mi >= 3) * 2;
}

// ============================================================================
// Kernel 1: Gram + channel sums via mma.sync. grid (GBLK, BATCH), 256 threads.
// Warp w handles k16 slice [16w,16w+16) of each staged 128-px tile; 20 upper
// tiles of the symmetric 64x64; cross-warp smem reduce + mirrored writeout.
// Channel sums accumulated in f32 during staging (exact means).
// Dynamic smem: 2 x 18432 B (h tiles, double-buffered); reused for reduction.
// ============================================================================
__device__ __forceinline__ void stage_g(unsigned short* hx,
                                        const float4* __restrict__ src,
                                        int tid, float s4[4]) {
#pragma unroll
    for (int r = 0; r < 8; ++r) {
        const int f = tid + 256 * r;       // 2048 float4 = 128 px x 16
        const float4 v = src[f];
        const int px = f >> 4, k0 = (f & 15) * 4;
        uint2 hp;
        hp.x = (uint32_t)bfh(v.x) | ((uint32_t)bfh(v.y) << 16);
        hp.y = (uint32_t)bfh(v.z) | ((uint32_t)bfh(v.w) << 16);
        *reinterpret_cast<uint2*>(hx + px * GXROW + k0) = hp;
        s4[0] += v.x; s4[1] += v.y; s4[2] += v.z; s4[3] += v.w;
    }
}

__global__ void __launch_bounds__(256) gram_mma_kernel(const float* __restrict__ x) {
    extern __shared__ char gsm[];
    unsigned short* XH[2] = {(unsigned short*)gsm,
                             (unsigned short*)(gsm + 18432)};
    __shared__ float ssum[256][4];

    const int tid = threadIdx.x, w = tid >> 5, lane = tid & 31;
    const int b = blockIdx.y, blk = blockIdx.x;

    const float4* x4 = reinterpret_cast<const float4*>(x) +
                       ((size_t)b * HW + (size_t)blk * GPIX) * (NCH / 4);

    float s4[4] = {0.f, 0.f, 0.f, 0.f};
    float C[20][4];
#pragma unroll
    for (int ti = 0; ti < 20; ++ti)
#pragma unroll
        for (int q = 0; q < 4; ++q) C[ti][q] = 0.f;

    stage_g(XH[0], x4, tid, s4);
    __syncthreads();

    const int kb = w * 16;
    // A (trans): groups -> quads m0k0, m8k0, m0k8, m8k8
    const int krow_a = (lane & 7) + ((lane >> 4) << 3);
    const int mcol_a = ((lane >> 3) & 1) << 3;
    // B (trans): groups -> quads k0n0, k8n0, k0n8, k8n8 (two n-tiles per load)
    const int krow_b = (lane & 7) + (((lane >> 3) & 1) << 3);
    const int ncol_b = (lane >> 4) << 3;

    for (int t = 0; t < GNT; ++t) {
        const int cb = t & 1;
        if (t + 1 < GNT) stage_g(XH[cb ^ 1], x4 + (size_t)(t + 1) * 2048, tid, s4);

        const uint32_t xs = smem_u32(XH[cb]);
        uint32_t ah[4][4];
#pragma unroll
        for (int mi = 0; mi < 4; ++mi)
            ldm4t(ah[mi], xs + (uint32_t)(((kb + krow_a) * GXROW +
                                           mi * 16 + mcol_a) * 2));
        uint32_t bh[8][2];
#pragma unroll
        for (int p = 0; p < 4; ++p) {
            uint32_t r[4];
            ldm4t(r, xs + (uint32_t)(((kb + krow_b) * GXROW +
                                      p * 16 + ncol_b) * 2));
            bh[2 * p][0] = r[0];     bh[2 * p][1] = r[1];
            bh[2 * p + 1][0] = r[2]; bh[2 * p + 1][1] = r[3];
        }
#pragma unroll
        for (int ti = 0; ti < 20; ++ti)
            mma_bf16(C[ti], ah[gmi(ti)], bh[gnj(ti)][0], bh[gnj(ti)][1]);
        __syncthreads();
    }

    // channel sums (f32-exact means)
#pragma unroll
    for (int j = 0; j < 4; ++j) ssum[tid][j] = s4[j];
    __syncthreads();
    if (tid < 64) {
        float s = 0.f;
#pragma unroll
        for (int g = 0; g < 16; ++g) s += ssum[g * 16 + (tid >> 2)][tid & 3];
        g_psum[b][blk][tid] = s;
    }

    // cross-warp reduce of C, 4 tiles per round; mirror writeout (i<=j rule)
    float* scr = (float*)gsm;
    for (int round = 0; round < 5; ++round) {
        __syncthreads();
#pragma unroll
        for (int rt = 0; rt < 4; ++rt) {
            const int ti = round * 4 + rt;
            float* dst = scr + ((rt * 8 + w) * 32 + lane) * 4;
            dst[0] = C[ti][0]; dst[1] = C[ti][1];
            dst[2] = C[ti][2]; dst[3] = C[ti][3];
        }
        __syncthreads();
        for (int e = tid; e < 512; e += 256) {
            const int rt = e >> 7, idx = e & 127, ln = idx >> 2, q = idx & 3;
            const int ti = round * 4 + rt;
            float v = 0.f;
#pragma unroll
            for (int ww = 0; ww < 8; ++ww)
                v += scr[((rt * 8 + ww) * 32 + ln) * 4 + q];
            const int i = gmi(ti) * 16 + (ln >> 2) + ((q >> 1) << 3);
            const int j = gnj(ti) * 8 + (ln & 3) * 2 + (q & 1);
            if (i <= j) {
                g_part[b][blk][i * 64 + j] = v;
                g_part[b][blk][j * 64 + i] = v;
            }
        }
    }
}

// ============================================================================
// 64x64 smem matmul helpers (stride MS), packed f32x2.
// ============================================================================
__device__ __forceinline__ void mm64p(const float* __restrict__ A,
                                      const float* __restrict__ B,
                                      unsigned long long r2[8], int i, int j0) {
#pragma unroll
    for (int q = 0; q < 8; q++) r2[q] = 0ull;
#pragma unroll 8
    for (int k = 0; k < 64; ++k) {
        unsigned long long ad = dup2f(A[i * MS + k]);
        const ulonglong2* b2 = reinterpret_cast<const ulonglong2*>(B + k * MS + j0);
        ulonglong2 x0 = b2[0], x1 = b2[1], x2 = b2[2], x3 = b2[3];
        ffma2(r2[0], ad, x0.x); ffma2(r2[1], ad, x0.y);
        ffma2(r2[2], ad, x1.x); ffma2(r2[3], ad, x1.y);
        ffma2(r2[4], ad, x2.x); ffma2(r2[5], ad, x2.y);
        ffma2(r2[6], ad, x3.x); ffma2(r2[7], ad, x3.y);
    }
}

__device__ __forceinline__ void mm64p8(const float* __restrict__ A,
                                       const float* __restrict__ B,
                                       unsigned long long r2[4], int i, int j0) {
#pragma unroll
    for (int q = 0; q < 4; q++) r2[q] = 0ull;
#pragma unroll 8
    for (int k = 0; k < 64; ++k) {
        unsigned long long ad = dup2f(A[i * MS + k]);
        const ulonglong2* b2 = reinterpret_cast<const ulonglong2*>(B + k * MS + j0);
        ulonglong2 x0 = b2[0], x1 = b2[1];
        ffma2(r2[0], ad, x0.x); ffma2(r2[1], ad, x0.y);
        ffma2(r2[2], ad, x1.x); ffma2(r2[3], ad, x1.y);
    }
}

// ============================================================================
// Kernel 2: fused cov-reduction + Newton-Schulz. grid BATCH, 512 threads.
// ============================================================================
__global__ void __launch_bounds__(512) ns_kernel() {
    extern __shared__ float dsm[];
    float* sY = dsm;
    float* sZ = sY + 64 * MS;
    float* sT = sZ + 64 * MS;
    __shared__ float mean_s[NCH];

    const int b = blockIdx.x, tid = threadIdx.x;
    const int i8  = tid >> 3, j8 = (tid & 7) * 8;
    const int u   = tid & 255;
    const int i16 = u >> 2, j16 = (u & 3) * 16;

    if (tid < NCH) {
        float s = 0.f;
#pragma unroll
        for (int k = 0; k < GBLK; ++k) s += g_psum[b][k][tid];
        float m = s * (1.f / (float)HW);
        mean_s[tid] = m;
        g_mean[b][tid] = m;
    }
    __syncthreads();

    const float inv_d = 1.f / (float)(HW - 1);
    for (int e = tid; e < 4096; e += 512) {
        float s = 0.f;
#pragma unroll
        for (int k = 0; k < GBLK; ++k) s += g_part[b][k][e];
        int i = e >> 6, j = e & 63;
        sZ[i * MS + j] = (s - (float)HW * mean_s[i] * mean_s[j]) * inv_d;
    }
    __syncthreads();

    if (tid < 64) {
        float s = 0.f;
        for (int j = 0; j < 64; ++j) s += fabsf(sZ[tid * MS + j]);
        sY[tid] = s;
    }
    __syncthreads();
    if (tid == 0) {
        float m = 0.f;
        for (int r = 0; r < 64; ++r) m = fmaxf(m, sY[r]);
        sT[0] = m;
    }
    __syncthreads();
    const float c = sT[0];
    const float inv_c = 1.f / c;
    __syncthreads();

    for (int e = tid; e < 4096; e += 512) {
        int r = e >> 6, q = e & 63;
        float v = sZ[r * MS + q];
        sY[r * MS + q] = v * inv_c;
        sZ[r * MS + q] = (r == q) ? 1.f : 0.f;
    }
    __syncthreads();

    for (int it = 0; it < NS_ITERS; ++it) {
        unsigned long long t2[4];
        mm64p8(sZ, sY, t2, i8, j8);
#pragma unroll
        for (int q = 0; q < 4; q++) {
            int j = j8 + 2 * q;
            sT[i8 * MS + j]     = ((i8 == j)     ? 1.5f : 0.f) - 0.5f * lo32(t2[q]);
            sT[i8 * MS + j + 1] = ((i8 == j + 1) ? 1.5f : 0.f) - 0.5f * hi32(t2[q]);
        }
        __syncthreads();

        unsigned long long r2[8];
        if (tid < 256) mm64p(sY, sT, r2, i16, j16);
        else           mm64p(sT, sZ, r2, i16, j16);
        __syncthreads();
        float* dst = (tid < 256) ? sY : sZ;
#pragma unroll
        for (int q = 0; q < 8; q++) {
            dst[i16 * MS + j16 + 2 * q]     = lo32(r2[q]);
            dst[i16 * MS + j16 + 2 * q + 1] = hi32(r2[q]);
        }
        __syncthreads();
    }

    const float sc = sqrtf(c), isc = rsqrtf(c);
    for (int e = tid; e < 4096; e += 512) {
        int r = e >> 6, q = e & 63;
        g_half[b][e] = sY[r * MS + q] * sc;
        g_invh[b][e] = sZ[r * MS + q] * isc;
    }
}

// ============================================================================
// Kernel 3: A_b (row-major) + bias_b. grid BATCH, 512 threads.
// ============================================================================
__global__ void __launch_bounds__(512) comb_kernel(const int* __restrict__ perm,
                                                   const float* __restrict__ alpha) {
    __shared__ float sS[64 * MS], sTi[64 * MS], red[512];
    const int b = blockIdx.x, tid = threadIdx.x;
    const int pb = perm[b];
    const float al = alpha[b];
    const float oma = 1.f - al;

    for (int e = tid; e < 4096; e += 512) {
        int r = e >> 6, q = e & 63;
        sS [r * MS + q] = g_half[pb][e];
        sTi[r * MS + q] = g_invh[b][e];
    }
    __syncthreads();

    const int i = tid >> 3, j0 = (tid & 7) * 8;
    unsigned long long m2[4];
    mm64p8(sS, sTi, m2, i, j0);

    float m[8];
#pragma unroll
    for (int q = 0; q < 4; q++) { m[2 * q] = lo32(m2[q]); m[2 * q + 1] = hi32(m2[q]); }

    float pdot = 0.f;
#pragma unroll
    for (int q = 0; q < 8; q++) {
        int j = j0 + q;
        g_A[b][i * 64 + j] = ((i == j) ? al : 0.f) + oma * m[q];
        pdot += m[q] * g_mean[b][j];
    }
    red[tid] = pdot;
    __syncthreads();
    if (tid < 64) {
        float dot = 0.f;
#pragma unroll
        for (int t = 0; t < 8; t++) dot += red[tid * 8 + t];
        g_bias[b][tid] = oma * (g_mean[pb][tid] - dot);
    }
}

// ============================================================================
// Kernel 4: out = A*x + bias via mma.sync bf16 split (passing R11 version).
// ============================================================================
#define SM_HX0  0
#define SM_HX1  18432
#define SM_LX0  36864
#define SM_LX1  55296
#define SM_AH   73728
#define SM_AL   82944
#define SM_BIAS 92160
#define APPLY_SMEM (SM_BIAS + 256)

__device__ __forceinline__ void stage_tile(unsigned short* hx, unsigned short* lx,
                                           const float4* __restrict__ src, int tid) {
#pragma unroll
    for (int r = 0; r < 8; ++r) {
        const int f = tid + 256 * r;
        const float4 v = src[f];
        const int px = f >> 4, k0 = (f & 15) * 4;
        unsigned short h0 = bfh(v.x), h1 = bfh(v.y), h2 = bfh(v.z), h3 = bfh(v.w);
        float r0 = v.x - __bfloat162float(__ushort_as_bfloat16(h0));
        float r1 = v.y - __bfloat162float(__ushort_as_bfloat16(h1));
        float r2 = v.z - __bfloat162float(__ushort_as_bfloat16(h2));
        float r3 = v.w - __bfloat162float(__ushort_as_bfloat16(h3));
        uint2 hp, lp;
        hp.x = (uint32_t)h0 | ((uint32_t)h1 << 16);
        hp.y = (uint32_t)h2 | ((uint32_t)h3 << 16);
        lp.x = (uint32_t)bfh(r0) | ((uint32_t)bfh(r1) << 16);
        lp.y = (uint32_t)bfh(r2) | ((uint32_t)bfh(r3) << 16);
        *reinterpret_cast<uint2*>(hx + px * XROW + k0) = hp;
        *reinterpret_cast<uint2*>(lx + px * XROW + k0) = lp;
    }
}

__global__ void __launch_bounds__(256) apply_mma_kernel(const float* __restrict__ x,
                                                        float* __restrict__ out) {
    extern __shared__ char smem[];
    unsigned short* HX[2] = {(unsigned short*)(smem + SM_HX0),
                             (unsigned short*)(smem + SM_HX1)};
    unsigned short* LX[2] = {(unsigned short*)(smem + SM_LX0),
                             (unsigned short*)(smem + SM_LX1)};
    unsigned short* AH = (unsigned short*)(smem + SM_AH);
    unsigned short* AL = (unsigned short*)(smem + SM_AL);
    float* sbias = (float*)(smem + SM_BIAS);

    const int tid = threadIdx.x;
    const int w = tid >> 5, lane = tid & 31;
    const int b = blockIdx.y, blk = blockIdx.x;

    for (int e = tid; e < 4096; e += 256) {
        const int c = e >> 6, k = e & 63;
        const float a = g_A[b][e];
        unsigned short h = bfh(a);
        float rl = a - __bfloat162float(__ushort_as_bfloat16(h));
        AH[c * AROW + k] = h;
        AL[c * AROW + k] = bfh(rl);
    }
    if (tid < 64) sbias[tid] = g_bias[b][tid];

    const float4* x4 = reinterpret_cast<const float4*>(x) +
                       ((size_t)b * HW + (size_t)blk * APB) * (NCH / 4);
    float* ob = out + ((size_t)b * HW + (size_t)blk * APB) * NCH;

    stage_tile(HX[0], LX[0], x4, tid);
    __syncthreads();

    const int pxb   = (w >> 1) * 32;
    const int nbase = (w & 1) * 32;
    uint32_t Bh[4][4][2], Bl[4][4][2];
    {
        const uint32_t ah_s = smem_u32(AH), al_s = smem_u32(AL);
        const int rown = nbase + (lane & 7) + ((lane >> 4) << 3);
        const int koff = ((lane >> 3) & 1) * 8;
#pragma unroll
        for (int ks = 0; ks < 4; ++ks)
#pragma unroll
            for (int ntp = 0; ntp < 2; ++ntp) {
                const uint32_t off =
                    (uint32_t)(((rown + ntp * 16) * AROW + ks * 16 + koff) * 2);
                uint32_t rh[4], rl[4];
                ldm4(rh, ah_s + off);
                ldm4(rl, al_s + off);
                Bh[ks][ntp * 2][0] = rh[0]; Bh[ks][ntp * 2][1] = rh[1];
                Bh[ks][ntp * 2 + 1][0] = rh[2]; Bh[ks][ntp * 2 + 1][1] = rh[3];
                Bl[ks][ntp * 2][0] = rl[0]; Bl[ks][ntp * 2][1] = rl[1];
                Bl[ks][ntp * 2 + 1][0] = rl[2]; Bl[ks][ntp * 2 + 1][1] = rl[3];
            }
    }

    float2 bv[4];
    {
        const int cpair = (lane & 3) * 2;
#pragma unroll
        for (int nt = 0; nt < 4; ++nt) {
            bv[nt].x = sbias[nbase + nt * 8 + cpair];
            bv[nt].y = sbias[nbase + nt * 8 + cpair + 1];
        }
    }

    const int xrow = (lane & 15);
    const int xkof = ((lane >> 4) << 3);

    for (int t = 0; t < NTIL; ++t) {
        const int cb = t & 1;

        if (t + 1 < NTIL)
            stage_tile(HX[cb ^ 1], LX[cb ^ 1], x4 + (size_t)(t + 1) * 2048, tid);

        const uint32_t hx_s = smem_u32(HX[cb]), lx_s = smem_u32(LX[cb]);

        float C[2][4][4];
#pragma unroll
        for (int mt = 0; mt < 2; ++mt)
#pragma unroll
            for (int nt = 0; nt < 4; ++nt)
#pragma unroll
                for (int q = 0; q < 4; ++q) C[mt][nt][q] = 0.f;

#pragma unroll
        for (int ks = 0; ks < 4; ++ks) {
            uint32_t ah[2][4], al[2][4];
#pragma unroll
            for (int mt = 0; mt < 2; ++mt) {
                const uint32_t off = (uint32_t)(
                    ((pxb + mt * 16 + xrow) * XROW + ks * 16 + xkof) * 2);
                ldm4(ah[mt], hx_s + off);
                ldm4(al[mt], lx_s + off);
            }
#pragma unroll
            for (int mt = 0; mt < 2; ++mt)
#pragma unroll
                for (int nt = 0; nt < 4; ++nt) {
                    mma_bf16(C[mt][nt], ah[mt], Bh[ks][nt][0], Bh[ks][nt][1]);
                    mma_bf16(C[mt][nt], al[mt], Bh[ks][nt][0], Bh[ks][nt][1]);
                    mma_bf16(C[mt][nt], ah[mt], Bl[ks][nt][0], Bl[ks][nt][1]);
                }
        }

        const int gr = lane >> 2, cpair = (lane & 3) * 2;
        const int pxg = t * ATL + pxb + gr;
#pragma unroll
        for (int mt = 0; mt < 2; ++mt) {
            float* row0 = ob + (size_t)(pxg + mt * 16) * NCH;
            float* row1 = row0 + 8 * NCH;
#pragma unroll
            for (int nt = 0; nt < 4; ++nt) {
                const int n = nbase + nt * 8 + cpair;
                *reinterpret_cast<float2*>(row0 + n) =
                    make_float2(C[mt][nt][0] + bv[nt].x, C[mt][nt][1] + bv[nt].y);
                *reinterpret_cast<float2*>(row1 + n) =
                    make_float2(C[mt][nt][2] + bv[nt].x, C[mt][nt][3] + bv[nt].y);
            }
        }
        __syncthreads();
    }
}

// ============================================================================
extern "C" void kernel_launch(void* const* d_in, const int* in_sizes, int n_in,
                              void* d_out, int out_size) {
    (void)in_sizes; (void)n_in; (void)out_size;
    const float* x     = (const float*)d_in[0];
    const int*   perm  = (const int*)d_in[1];
    const float* alpha = (const float*)d_in[2];
    float*       out   = (float*)d_out;

    const int ns_smem   = 3 * 64 * MS * (int)sizeof(float);   // 52224 B
    const int gram_smem = 2 * 18432;                          // 36864 B
    cudaFuncSetAttribute(ns_kernel, cudaFuncAttributeMaxDynamicSharedMemorySize, ns_smem);
    cudaFuncSetAttribute(apply_mma_kernel, cudaFuncAttributeMaxDynamicSharedMemorySize,
                         APPLY_SMEM);

    gram_mma_kernel<<<dim3(GBLK, BATCH), 256, gram_smem>>>(x);
    ns_kernel<<<BATCH, 512, ns_smem>>>();
    comb_kernel<<<BATCH, 512>>>(perm, alpha);
    apply_mma_kernel<<<dim3(ABLKS, BATCH), 256, APPLY_SMEM>>>(x, out);
}

// round 14
// speedup vs baseline: 2.2081x; 1.0606x over previous
#include <cuda_runtime.h>
#include <cuda_bf16.h>
#include <cstdint>

// WCT folded: out = A_b * x + bias_b, A_b = alpha*I + (1-alpha)*M_b,
// M_b = cov_{perm[b]}^{1/2} * cov_b^{-1/2} via coupled Newton-Schulz.
// R13: LDG-prefetch-then-compute reorder in gram/apply (DRAM latency hidden
//      under mma), GBLK/ABLKS=32, ns at 1024 threads, NS_ITERS=5.

#define BATCH 16
#define HW 65536
#define NCH 64
#define GBLK 32
#define GPIX (HW / GBLK)        // 2048
#define NS_ITERS 5
#define MS 68

// apply config
#define ABLKS 32
#define APB   2048
#define ATL   128
#define NTIL  (APB / ATL)       // 16
#define XROW  72
#define AROW  72

// gram config
#define GXROW 72
#define GNT   (GPIX / 128)      // 16 staged tiles per block

// ---- device scratch ----
__device__ float g_part[BATCH][GBLK][NCH * NCH];
__device__ float g_psum[BATCH][GBLK][NCH];
__device__ float g_mean[BATCH][NCH];
__device__ float g_half[BATCH][NCH * NCH];
__device__ float g_invh[BATCH][NCH * NCH];
__device__ float g_A  [BATCH][NCH * NCH];          // row-major: g_A[c*64+k]
__device__ float g_bias[BATCH][NCH];

// ---- packed f32x2 helpers (ns/comb) ----
__device__ __forceinline__ void ffma2(unsigned long long& d,
                                      unsigned long long a,
                                      unsigned long long b) {
    asm("fma.rn.f32x2 %0, %1, %2, %0;" : "+l"(d) : "l"(a), "l"(b));
}
__device__ __forceinline__ unsigned long long dup2f(float v) {
    unsigned long long r;
    unsigned u = __float_as_uint(v);
    asm("mov.b64 %0, {%1, %1};" : "=l"(r) : "r"(u));
    return r;
}
__device__ __forceinline__ float lo32(unsigned long long v) {
    return __uint_as_float((unsigned)v);
}
__device__ __forceinline__ float hi32(unsigned long long v) {
    return __uint_as_float((unsigned)(v >> 32));
}

// ---- warp mma helpers ----
__device__ __forceinline__ uint32_t smem_u32(const void* p) {
    return (uint32_t)__cvta_generic_to_shared(p);
}
__device__ __forceinline__ void ldm4(uint32_t r[4], uint32_t addr) {
    asm volatile("ldmatrix.sync.aligned.m8n8.x4.shared.b16 {%0,%1,%2,%3}, [%4];"
                 : "=r"(r[0]), "=r"(r[1]), "=r"(r[2]), "=r"(r[3]) : "r"(addr));
}
__device__ __forceinline__ void ldm4t(uint32_t r[4], uint32_t addr) {
    asm volatile("ldmatrix.sync.aligned.m8n8.x4.trans.shared.b16 {%0,%1,%2,%3}, [%4];"
                 : "=r"(r[0]), "=r"(r[1]), "=r"(r[2]), "=r"(r[3]) : "r"(addr));
}
__device__ __forceinline__ void mma_bf16(float c[4], const uint32_t a[4],
                                         const uint32_t b0, const uint32_t b1) {
    asm volatile(
        "mma.sync.aligned.m16n8k16.row.col.f32.bf16.bf16.f32 "
        "{%0,%1,%2,%3}, {%4,%5,%6,%7}, {%8,%9}, {%0,%1,%2,%3};"
        : "+f"(c[0]), "+f"(c[1]), "+f"(c[2]), "+f"(c[3])
        : "r"(a[0]), "r"(a[1]), "r"(a[2]), "r"(a[3]), "r"(b0), "r"(b1));
}
__device__ __forceinline__ unsigned short bfh(float v) {
    return __bfloat16_as_ushort(__float2bfloat16_rn(v));
}

// upper-triangle m16n8 tile list: 20 tiles (mi 0..3, nj >= 2*mi)
__device__ __forceinline__ int gmi(int ti) {
    return (ti >= 8) + (ti >= 14) + (ti >= 18);
}
__device__ __forceinline__ int gnj(int ti) {
    int mi = gmi(ti);
    return ti - (mi >= 1) * 6 - (mi >= 2) * 4 - (mi >= 3) * 2;
}

// ============================================================================
// Kernel 1: Gram + channel sums via mma.sync. grid (GBLK, BATCH), 256 threads.
// Prefetch-first ordering: next tile's LDGs issue before this tile's mma,
// so DRAM latency hides under tensor work; only cvt+STS is exposed.
// ============================================================================
__device__ __forceinline__ void g_load(float4 pf[8], const float4* __restrict__ src,
                                       int tid) {
#pragma unroll
    for (int r = 0; r < 8; ++r) pf[r] = src[tid + 256 * r];
}
__device__ __forceinline__ void g_store(unsigned short* hx, const float4 pf[8],
                                        int tid, float s4[4]) {
#pragma unroll
    for (int r = 0; r < 8; ++r) {
        const int f = tid + 256 * r;
        const float4 v = pf[r];
        const int px = f >> 4, k0 = (f & 15) * 4;
        uint2 hp;
        hp.x = (uint32_t)bfh(v.x) | ((uint32_t)bfh(v.y) << 16);
        hp.y = (uint32_t)bfh(v.z) | ((uint32_t)bfh(v.w) << 16);
        *reinterpret_cast<uint2*>(hx + px * GXROW + k0) = hp;
        s4[0] += v.x; s4[1] += v.y; s4[2] += v.z; s4[3] += v.w;
    }
}

__global__ void __launch_bounds__(256) gram_mma_kernel(const float* __restrict__ x) {
    extern __shared__ char gsm[];
    unsigned short* XH[2] = {(unsigned short*)gsm,
                             (unsigned short*)(gsm + 18432)};
    __shared__ float ssum[256][4];

    const int tid = threadIdx.x, w = tid >> 5, lane = tid & 31;
    const int b = blockIdx.y, blk = blockIdx.x;

    const float4* x4 = reinterpret_cast<const float4*>(x) +
                       ((size_t)b * HW + (size_t)blk * GPIX) * (NCH / 4);

    float s4[4] = {0.f, 0.f, 0.f, 0.f};
    float C[20][4];
#pragma unroll
    for (int ti = 0; ti < 20; ++ti)
#pragma unroll
        for (int q = 0; q < 4; ++q) C[ti][q] = 0.f;

    float4 pf[8];
    g_load(pf, x4, tid);
    g_store(XH[0], pf, tid, s4);
    __syncthreads();

    const int kb = w * 16;
    const int krow_a = (lane & 7) + ((lane >> 4) << 3);
    const int mcol_a = ((lane >> 3) & 1) << 3;
    const int krow_b = (lane & 7) + (((lane >> 3) & 1) << 3);
    const int ncol_b = (lane >> 4) << 3;

    for (int t = 0; t < GNT; ++t) {
        const int cb = t & 1;
        if (t + 1 < GNT) g_load(pf, x4 + (size_t)(t + 1) * 2048, tid);

        const uint32_t xs = smem_u32(XH[cb]);
        uint32_t ah[4][4];
#pragma unroll
        for (int mi = 0; mi < 4; ++mi)
            ldm4t(ah[mi], xs + (uint32_t)(((kb + krow_a) * GXROW +
                                           mi * 16 + mcol_a) * 2));
        uint32_t bh[8][2];
#pragma unroll
        for (int p = 0; p < 4; ++p) {
            uint32_t r[4];
            ldm4t(r, xs + (uint32_t)(((kb + krow_b) * GXROW +
                                      p * 16 + ncol_b) * 2));
            bh[2 * p][0] = r[0];     bh[2 * p][1] = r[1];
            bh[2 * p + 1][0] = r[2]; bh[2 * p + 1][1] = r[3];
        }
#pragma unroll
        for (int ti = 0; ti < 20; ++ti)
            mma_bf16(C[ti], ah[gmi(ti)], bh[gnj(ti)][0], bh[gnj(ti)][1]);
        __syncthreads();                 // reads of XH[cb] done; XH[cb^1] free

        if (t + 1 < GNT) {
            g_store(XH[cb ^ 1], pf, tid, s4);
            __syncthreads();
        }
    }

    // channel sums (f32-exact means)
#pragma unroll
    for (int j = 0; j < 4; ++j) ssum[tid][j] = s4[j];
    __syncthreads();
    if (tid < 64) {
        float s = 0.f;
#pragma unroll
        for (int g = 0; g < 16; ++g) s += ssum[g * 16 + (tid >> 2)][tid & 3];
        g_psum[b][blk][tid] = s;
    }

    // cross-warp reduce of C, 4 tiles per round; mirror writeout (i<=j rule)
    float* scr = (float*)gsm;
    for (int round = 0; round < 5; ++round) {
        __syncthreads();
#pragma unroll
        for (int rt = 0; rt < 4; ++rt) {
            const int ti = round * 4 + rt;
            float* dst = scr + ((rt * 8 + w) * 32 + lane) * 4;
            dst[0] = C[ti][0]; dst[1] = C[ti][1];
            dst[2] = C[ti][2]; dst[3] = C[ti][3];
        }
        __syncthreads();
        for (int e = tid; e < 512; e += 256) {
            const int rt = e >> 7, idx = e & 127, ln = idx >> 2, q = idx & 3;
            const int ti = round * 4 + rt;
            float v = 0.f;
#pragma unroll
            for (int ww = 0; ww < 8; ++ww)
                v += scr[((rt * 8 + ww) * 32 + ln) * 4 + q];
            const int i = gmi(ti) * 16 + (ln >> 2) + ((q >> 1) << 3);
            const int j = gnj(ti) * 8 + (ln & 3) * 2 + (q & 1);
            if (i <= j) {
                g_part[b][blk][i * 64 + j] = v;
                g_part[b][blk][j * 64 + i] = v;
            }
        }
    }
}

// ============================================================================
// 64x64 smem matmul helpers (stride MS), packed f32x2.
// ============================================================================
__device__ __forceinline__ void mm64p8(const float* __restrict__ A,
                                       const float* __restrict__ B,
                                       unsigned long long r2[4], int i, int j0) {
#pragma unroll
    for (int q = 0; q < 4; q++) r2[q] = 0ull;
#pragma unroll 8
    for (int k = 0; k < 64; ++k) {
        unsigned long long ad = dup2f(A[i * MS + k]);
        const ulonglong2* b2 = reinterpret_cast<const ulonglong2*>(B + k * MS + j0);
        ulonglong2 x0 = b2[0], x1 = b2[1];
        ffma2(r2[0], ad, x0.x); ffma2(r2[1], ad, x0.y);
        ffma2(r2[2], ad, x1.x); ffma2(r2[3], ad, x1.y);
    }
}

__device__ __forceinline__ void mm64p4(const float* __restrict__ A,
                                       const float* __restrict__ B,
                                       unsigned long long r2[2], int i, int j0) {
    r2[0] = 0ull; r2[1] = 0ull;
#pragma unroll 8
    for (int k = 0; k < 64; ++k) {
        unsigned long long ad = dup2f(A[i * MS + k]);
        const ulonglong2* b2 = reinterpret_cast<const ulonglong2*>(B + k * MS + j0);
        ulonglong2 x0 = b2[0];
        ffma2(r2[0], ad, x0.x); ffma2(r2[1], ad, x0.y);
    }
}

// ============================================================================
// Kernel 2: fused cov-reduction + Newton-Schulz. grid BATCH, 1024 threads.
// T-phase 4-wide on all 1024; Y*T / T*Z concurrently on 512-thread halves.
// ============================================================================
__global__ void __launch_bounds__(1024) ns_kernel() {
    extern __shared__ float dsm[];
    float* sY = dsm;
    float* sZ = sY + 64 * MS;
    float* sT = sZ + 64 * MS;
    __shared__ float mean_s[NCH];

    const int b = blockIdx.x, tid = threadIdx.x;
    const int i4 = tid >> 4, j4 = (tid & 15) * 4;            // T-phase mapping
    const int u  = tid & 511;
    const int i8 = u >> 3, j8 = (u & 7) * 8;                 // half-phase mapping

    if (tid < NCH) {
        float s = 0.f;
#pragma unroll
        for (int k = 0; k < GBLK; ++k) s += g_psum[b][k][tid];
        float m = s * (1.f / (float)HW);
        mean_s[tid] = m;
        g_mean[b][tid] = m;
    }
    __syncthreads();

    const float inv_d = 1.f / (float)(HW - 1);
    for (int e = tid; e < 4096; e += 1024) {
        float s = 0.f;
#pragma unroll
        for (int k = 0; k < GBLK; ++k) s += g_part[b][k][e];
        int i = e >> 6, j = e & 63;
        sZ[i * MS + j] = (s - (float)HW * mean_s[i] * mean_s[j]) * inv_d;
    }
    __syncthreads();

    if (tid < 64) {
        float s = 0.f;
        for (int j = 0; j < 64; ++j) s += fabsf(sZ[tid * MS + j]);
        sY[tid] = s;
    }
    __syncthreads();
    if (tid == 0) {
        float m = 0.f;
        for (int r = 0; r < 64; ++r) m = fmaxf(m, sY[r]);
        sT[0] = m;
    }
    __syncthreads();
    const float c = sT[0];
    const float inv_c = 1.f / c;
    __syncthreads();

    for (int e = tid; e < 4096; e += 1024) {
        int r = e >> 6, q = e & 63;
        float v = sZ[r * MS + q];
        sY[r * MS + q] = v * inv_c;
        sZ[r * MS + q] = (r == q) ? 1.f : 0.f;
    }
    __syncthreads();

    for (int it = 0; it < NS_ITERS; ++it) {
        // T = 1.5 I - 0.5 * Z*Y   (all 1024 threads, 4-wide)
        unsigned long long t2[2];
        mm64p4(sZ, sY, t2, i4, j4);
#pragma unroll
        for (int q = 0; q < 2; q++) {
            int j = j4 + 2 * q;
            sT[i4 * MS + j]     = ((i4 == j)     ? 1.5f : 0.f) - 0.5f * lo32(t2[q]);
            sT[i4 * MS + j + 1] = ((i4 == j + 1) ? 1.5f : 0.f) - 0.5f * hi32(t2[q]);
        }
        __syncthreads();

        // Y' = Y*T (tid<512), Z' = T*Z (tid>=512), concurrent
        unsigned long long r2[4];
        if (tid < 512) mm64p8(sY, sT, r2, i8, j8);
        else           mm64p8(sT, sZ, r2, i8, j8);
        __syncthreads();
        float* dst = (tid < 512) ? sY : sZ;
#pragma unroll
        for (int q = 0; q < 4; q++) {
            dst[i8 * MS + j8 + 2 * q]     = lo32(r2[q]);
            dst[i8 * MS + j8 + 2 * q + 1] = hi32(r2[q]);
        }
        __syncthreads();
    }

    const float sc = sqrtf(c), isc = rsqrtf(c);
    for (int e = tid; e < 4096; e += 1024) {
        int r = e >> 6, q = e & 63;
        g_half[b][e] = sY[r * MS + q] * sc;
        g_invh[b][e] = sZ[r * MS + q] * isc;
    }
}

// ============================================================================
// Kernel 3: A_b (row-major) + bias_b. grid BATCH, 512 threads.
// ============================================================================
__global__ void __launch_bounds__(512) comb_kernel(const int* __restrict__ perm,
                                                   const float* __restrict__ alpha) {
    __shared__ float sS[64 * MS], sTi[64 * MS], red[512];
    const int b = blockIdx.x, tid = threadIdx.x;
    const int pb = perm[b];
    const float al = alpha[b];
    const float oma = 1.f - al;

    for (int e = tid; e < 4096; e += 512) {
        int r = e >> 6, q = e & 63;
        sS [r * MS + q] = g_half[pb][e];
        sTi[r * MS + q] = g_invh[b][e];
    }
    __syncthreads();

    const int i = tid >> 3, j0 = (tid & 7) * 8;
    unsigned long long m2[4];
    mm64p8(sS, sTi, m2, i, j0);

    float m[8];
#pragma unroll
    for (int q = 0; q < 4; q++) { m[2 * q] = lo32(m2[q]); m[2 * q + 1] = hi32(m2[q]); }

    float pdot = 0.f;
#pragma unroll
    for (int q = 0; q < 8; q++) {
        int j = j0 + q;
        g_A[b][i * 64 + j] = ((i == j) ? al : 0.f) + oma * m[q];
        pdot += m[q] * g_mean[b][j];
    }
    red[tid] = pdot;
    __syncthreads();
    if (tid < 64) {
        float dot = 0.f;
#pragma unroll
        for (int t = 0; t < 8; t++) dot += red[tid * 8 + t];
        g_bias[b][tid] = oma * (g_mean[pb][tid] - dot);
    }
}

// ============================================================================
// Kernel 4: out = A*x + bias via mma.sync bf16 split, prefetch-first staging.
// grid (ABLKS, BATCH), 256 threads.
// ============================================================================
#define SM_HX0  0
#define SM_HX1  18432
#define SM_LX0  36864
#define SM_LX1  55296
#define SM_AH   73728
#define SM_AL   82944
#define SM_BIAS 92160
#define APPLY_SMEM (SM_BIAS + 256)

__device__ __forceinline__ void a_store(unsigned short* hx, unsigned short* lx,
                                        const float4 pf[8], int tid) {
#pragma unroll
    for (int r = 0; r < 8; ++r) {
        const int f = tid + 256 * r;
        const float4 v = pf[r];
        const int px = f >> 4, k0 = (f & 15) * 4;
        unsigned short h0 = bfh(v.x), h1 = bfh(v.y), h2 = bfh(v.z), h3 = bfh(v.w);
        float r0 = v.x - __bfloat162float(__ushort_as_bfloat16(h0));
        float r1 = v.y - __bfloat162float(__ushort_as_bfloat16(h1));
        float r2 = v.z - __bfloat162float(__ushort_as_bfloat16(h2));
        float r3 = v.w - __bfloat162float(__ushort_as_bfloat16(h3));
        uint2 hp, lp;
        hp.x = (uint32_t)h0 | ((uint32_t)h1 << 16);
        hp.y = (uint32_t)h2 | ((uint32_t)h3 << 16);
        lp.x = (uint32_t)bfh(r0) | ((uint32_t)bfh(r1) << 16);
        lp.y = (uint32_t)bfh(r2) | ((uint32_t)bfh(r3) << 16);
        *reinterpret_cast<uint2*>(hx + px * XROW + k0) = hp;
        *reinterpret_cast<uint2*>(lx + px * XROW + k0) = lp;
    }
}

__global__ void __launch_bounds__(256) apply_mma_kernel(const float* __restrict__ x,
                                                        float* __restrict__ out) {
    extern __shared__ char smem[];
    unsigned short* HX[2] = {(unsigned short*)(smem + SM_HX0),
                             (unsigned short*)(smem + SM_HX1)};
    unsigned short* LX[2] = {(unsigned short*)(smem + SM_LX0),
                             (unsigned short*)(smem + SM_LX1)};
    unsigned short* AH = (unsigned short*)(smem + SM_AH);
    unsigned short* AL = (unsigned short*)(smem + SM_AL);
    float* sbias = (float*)(smem + SM_BIAS);

    const int tid = threadIdx.x;
    const int w = tid >> 5, lane = tid & 31;
    const int b = blockIdx.y, blk = blockIdx.x;

    for (int e = tid; e < 4096; e += 256) {
        const int c = e >> 6, k = e & 63;
        const float a = g_A[b][e];
        unsigned short h = bfh(a);
        float rl = a - __bfloat162float(__ushort_as_bfloat16(h));
        AH[c * AROW + k] = h;
        AL[c * AROW + k] = bfh(rl);
    }
    if (tid < 64) sbias[tid] = g_bias[b][tid];

    const float4* x4 = reinterpret_cast<const float4*>(x) +
                       ((size_t)b * HW + (size_t)blk * APB) * (NCH / 4);
    float* ob = out + ((size_t)b * HW + (size_t)blk * APB) * NCH;

    float4 pf[8];
    g_load(pf, x4, tid);
    a_store(HX[0], LX[0], pf, tid);
    __syncthreads();

    const int pxb   = (w >> 1) * 32;
    const int nbase = (w & 1) * 32;
    uint32_t Bh[4][4][2], Bl[4][4][2];
    {
        const uint32_t ah_s = smem_u32(AH), al_s = smem_u32(AL);
        const int rown = nbase + (lane & 7) + ((lane >> 4) << 3);
        const int koff = ((lane >> 3) & 1) * 8;
#pragma unroll
        for (int ks = 0; ks < 4; ++ks)
#pragma unroll
            for (int ntp = 0; ntp < 2; ++ntp) {
                const uint32_t off =
                    (uint32_t)(((rown + ntp * 16) * AROW + ks * 16 + koff) * 2);
                uint32_t rh[4], rl[4];
                ldm4(rh, ah_s + off);
                ldm4(rl, al_s + off);
                Bh[ks][ntp * 2][0] = rh[0]; Bh[ks][ntp * 2][1] = rh[1];
                Bh[ks][ntp * 2 + 1][0] = rh[2]; Bh[ks][ntp * 2 + 1][1] = rh[3];
                Bl[ks][ntp * 2][0] = rl[0]; Bl[ks][ntp * 2][1] = rl[1];
                Bl[ks][ntp * 2 + 1][0] = rl[2]; Bl[ks][ntp * 2 + 1][1] = rl[3];
            }
    }

    float2 bv[4];
    {
        const int cpair = (lane & 3) * 2;
#pragma unroll
        for (int nt = 0; nt < 4; ++nt) {
            bv[nt].x = sbias[nbase + nt * 8 + cpair];
            bv[nt].y = sbias[nbase + nt * 8 + cpair + 1];
        }
    }

    const int xrow = (lane & 15);
    const int xkof = ((lane >> 4) << 3);

    for (int t = 0; t < NTIL; ++t) {
        const int cb = t & 1;

        if (t + 1 < NTIL) g_load(pf, x4 + (size_t)(t + 1) * 2048, tid);

        const uint32_t hx_s = smem_u32(HX[cb]), lx_s = smem_u32(LX[cb]);

        float C[2][4][4];
#pragma unroll
        for (int mt = 0; mt < 2; ++mt)
#pragma unroll
            for (int nt = 0; nt < 4; ++nt)
#pragma unroll
                for (int q = 0; q < 4; ++q) C[mt][nt][q] = 0.f;

#pragma unroll
        for (int ks = 0; ks < 4; ++ks) {
            uint32_t ah[2][4], al[2][4];
#pragma unroll
            for (int mt = 0; mt < 2; ++mt) {
                const uint32_t off = (uint32_t)(
                    ((pxb + mt * 16 + xrow) * XROW + ks * 16 + xkof) * 2);
                ldm4(ah[mt], hx_s + off);
                ldm4(al[mt], lx_s + off);
            }
#pragma unroll
            for (int mt = 0; mt < 2; ++mt)
#pragma unroll
                for (int nt = 0; nt < 4; ++nt) {
                    mma_bf16(C[mt][nt], ah[mt], Bh[ks][nt][0], Bh[ks][nt][1]);
                    mma_bf16(C[mt][nt], al[mt], Bh[ks][nt][0], Bh[ks][nt][1]);
                    mma_bf16(C[mt][nt], ah[mt], Bl[ks][nt][0], Bl[ks][nt][1]);
                }
        }

        const int gr = lane >> 2, cpair = (lane & 3) * 2;
        const int pxg = t * ATL + pxb + gr;
#pragma unroll
        for (int mt = 0; mt < 2; ++mt) {
            float* row0 = ob + (size_t)(pxg + mt * 16) * NCH;
            float* row1 = row0 + 8 * NCH;
#pragma unroll
            for (int nt = 0; nt < 4; ++nt) {
                const int n = nbase + nt * 8 + cpair;
                *reinterpret_cast<float2*>(row0 + n) =
                    make_float2(C[mt][nt][0] + bv[nt].x, C[mt][nt][1] + bv[nt].y);
                *reinterpret_cast<float2*>(row1 + n) =
                    make_float2(C[mt][nt][2] + bv[nt].x, C[mt][nt][3] + bv[nt].y);
            }
        }
        __syncthreads();                 // reads of HX/LX[cb] done

        if (t + 1 < NTIL) {
            a_store(HX[cb ^ 1], LX[cb ^ 1], pf, tid);
            __syncthreads();
        }
    }
}

// ============================================================================
extern "C" void kernel_launch(void* const* d_in, const int* in_sizes, int n_in,
                              void* d_out, int out_size) {
    (void)in_sizes; (void)n_in; (void)out_size;
    const float* x     = (const float*)d_in[0];
    const int*   perm  = (const int*)d_in[1];
    const float* alpha = (const float*)d_in[2];
    float*       out   = (float*)d_out;

    const int ns_smem   = 3 * 64 * MS * (int)sizeof(float);   // 52224 B
    const int gram_smem = 2 * 18432;                          // 36864 B
    cudaFuncSetAttribute(ns_kernel, cudaFuncAttributeMaxDynamicSharedMemorySize, ns_smem);
    cudaFuncSetAttribute(apply_mma_kernel, cudaFuncAttributeMaxDynamicSharedMemorySize,
                         APPLY_SMEM);

    gram_mma_kernel<<<dim3(GBLK, BATCH), 256, gram_smem>>>(x);
    ns_kernel<<<BATCH, 1024, ns_smem>>>();
    comb_kernel<<<BATCH, 512>>>(perm, alpha);
    apply_mma_kernel<<<dim3(ABLKS, BATCH), 256, APPLY_SMEM>>>(x, out);
}

// round 15
// speedup vs baseline: 2.4044x; 1.0889x over previous
#include <cuda_runtime.h>
#include <cuda_bf16.h>
#include <cstdint>

// WCT folded: out = A_b * x + bias_b, A_b = alpha*I + (1-alpha)*M_b,
// M_b = cov_{perm[b]}^{1/2} * cov_b^{-1/2} via coupled Newton-Schulz.
// R14: keep R13 wins (gram prefetch + GBLK=32, ns@1024, NS_ITERS=5);
//      revert apply to the exact R12 kernel (128 regs, 2 blocks/SM) with
//      __launch_bounds__(256,2) pinning the register budget.

#define BATCH 16
#define HW 65536
#define NCH 64
#define GBLK 32
#define GPIX (HW / GBLK)        // 2048
#define NS_ITERS 5
#define MS 68

// apply config (R12)
#define ABLKS 16
#define APB   4096
#define ATL   128
#define NTIL  (APB / ATL)       // 32
#define XROW  72
#define AROW  72

// gram config
#define GXROW 72
#define GNT   (GPIX / 128)      // 16 staged tiles per block

// ---- device scratch ----
__device__ float g_part[BATCH][GBLK][NCH * NCH];
__device__ float g_psum[BATCH][GBLK][NCH];
__device__ float g_mean[BATCH][NCH];
__device__ float g_half[BATCH][NCH * NCH];
__device__ float g_invh[BATCH][NCH * NCH];
__device__ float g_A  [BATCH][NCH * NCH];          // row-major: g_A[c*64+k]
__device__ float g_bias[BATCH][NCH];

// ---- packed f32x2 helpers (ns/comb) ----
__device__ __forceinline__ void ffma2(unsigned long long& d,
                                      unsigned long long a,
                                      unsigned long long b) {
    asm("fma.rn.f32x2 %0, %1, %2, %0;" : "+l"(d) : "l"(a), "l"(b));
}
__device__ __forceinline__ unsigned long long dup2f(float v) {
    unsigned long long r;
    unsigned u = __float_as_uint(v);
    asm("mov.b64 %0, {%1, %1};" : "=l"(r) : "r"(u));
    return r;
}
__device__ __forceinline__ float lo32(unsigned long long v) {
    return __uint_as_float((unsigned)v);
}
__device__ __forceinline__ float hi32(unsigned long long v) {
    return __uint_as_float((unsigned)(v >> 32));
}

// ---- warp mma helpers ----
__device__ __forceinline__ uint32_t smem_u32(const void* p) {
    return (uint32_t)__cvta_generic_to_shared(p);
}
__device__ __forceinline__ void ldm4(uint32_t r[4], uint32_t addr) {
    asm volatile("ldmatrix.sync.aligned.m8n8.x4.shared.b16 {%0,%1,%2,%3}, [%4];"
                 : "=r"(r[0]), "=r"(r[1]), "=r"(r[2]), "=r"(r[3]) : "r"(addr));
}
__device__ __forceinline__ void ldm4t(uint32_t r[4], uint32_t addr) {
    asm volatile("ldmatrix.sync.aligned.m8n8.x4.trans.shared.b16 {%0,%1,%2,%3}, [%4];"
                 : "=r"(r[0]), "=r"(r[1]), "=r"(r[2]), "=r"(r[3]) : "r"(addr));
}
__device__ __forceinline__ void mma_bf16(float c[4], const uint32_t a[4],
                                         const uint32_t b0, const uint32_t b1) {
    asm volatile(
        "mma.sync.aligned.m16n8k16.row.col.f32.bf16.bf16.f32 "
        "{%0,%1,%2,%3}, {%4,%5,%6,%7}, {%8,%9}, {%0,%1,%2,%3};"
        : "+f"(c[0]), "+f"(c[1]), "+f"(c[2]), "+f"(c[3])
        : "r"(a[0]), "r"(a[1]), "r"(a[2]), "r"(a[3]), "r"(b0), "r"(b1));
}
__device__ __forceinline__ unsigned short bfh(float v) {
    return __bfloat16_as_ushort(__float2bfloat16_rn(v));
}

// upper-triangle m16n8 tile list: 20 tiles (mi 0..3, nj >= 2*mi)
__device__ __forceinline__ int gmi(int ti) {
    return (ti >= 8) + (ti >= 14) + (ti >= 18);
}
__device__ __forceinline__ int gnj(int ti) {
    int mi = gmi(ti);
    return ti - (mi >= 1) * 6 - (mi >= 2) * 4 - (mi >= 3) * 2;
}

// ============================================================================
// Kernel 1: Gram + channel sums via mma.sync. grid (GBLK, BATCH), 256 threads.
// Prefetch-first ordering (R13): next tile's LDGs issue before this tile's
// mma, so DRAM latency hides under tensor work.
// ============================================================================
__device__ __forceinline__ void g_load(float4 pf[8], const float4* __restrict__ src,
                                       int tid) {
#pragma unroll
    for (int r = 0; r < 8; ++r) pf[r] = src[tid + 256 * r];
}
__device__ __forceinline__ void g_store(unsigned short* hx, const float4 pf[8],
                                        int tid, float s4[4]) {
#pragma unroll
    for (int r = 0; r < 8; ++r) {
        const int f = tid + 256 * r;
        const float4 v = pf[r];
        const int px = f >> 4, k0 = (f & 15) * 4;
        uint2 hp;
        hp.x = (uint32_t)bfh(v.x) | ((uint32_t)bfh(v.y) << 16);
        hp.y = (uint32_t)bfh(v.z) | ((uint32_t)bfh(v.w) << 16);
        *reinterpret_cast<uint2*>(hx + px * GXROW + k0) = hp;
        s4[0] += v.x; s4[1] += v.y; s4[2] += v.z; s4[3] += v.w;
    }
}

__global__ void __launch_bounds__(256) gram_mma_kernel(const float* __restrict__ x) {
    extern __shared__ char gsm[];
    unsigned short* XH[2] = {(unsigned short*)gsm,
                             (unsigned short*)(gsm + 18432)};
    __shared__ float ssum[256][4];

    const int tid = threadIdx.x, w = tid >> 5, lane = tid & 31;
    const int b = blockIdx.y, blk = blockIdx.x;

    const float4* x4 = reinterpret_cast<const float4*>(x) +
                       ((size_t)b * HW + (size_t)blk * GPIX) * (NCH / 4);

    float s4[4] = {0.f, 0.f, 0.f, 0.f};
    float C[20][4];
#pragma unroll
    for (int ti = 0; ti < 20; ++ti)
#pragma unroll
        for (int q = 0; q < 4; ++q) C[ti][q] = 0.f;

    float4 pf[8];
    g_load(pf, x4, tid);
    g_store(XH[0], pf, tid, s4);
    __syncthreads();

    const int kb = w * 16;
    const int krow_a = (lane & 7) + ((lane >> 4) << 3);
    const int mcol_a = ((lane >> 3) & 1) << 3;
    const int krow_b = (lane & 7) + (((lane >> 3) & 1) << 3);
    const int ncol_b = (lane >> 4) << 3;

    for (int t = 0; t < GNT; ++t) {
        const int cb = t & 1;
        if (t + 1 < GNT) g_load(pf, x4 + (size_t)(t + 1) * 2048, tid);

        const uint32_t xs = smem_u32(XH[cb]);
        uint32_t ah[4][4];
#pragma unroll
        for (int mi = 0; mi < 4; ++mi)
            ldm4t(ah[mi], xs + (uint32_t)(((kb + krow_a) * GXROW +
                                           mi * 16 + mcol_a) * 2));
        uint32_t bh[8][2];
#pragma unroll
        for (int p = 0; p < 4; ++p) {
            uint32_t r[4];
            ldm4t(r, xs + (uint32_t)(((kb + krow_b) * GXROW +
                                      p * 16 + ncol_b) * 2));
            bh[2 * p][0] = r[0];     bh[2 * p][1] = r[1];
            bh[2 * p + 1][0] = r[2]; bh[2 * p + 1][1] = r[3];
        }
#pragma unroll
        for (int ti = 0; ti < 20; ++ti)
            mma_bf16(C[ti], ah[gmi(ti)], bh[gnj(ti)][0], bh[gnj(ti)][1]);
        __syncthreads();                 // reads of XH[cb] done; XH[cb^1] free

        if (t + 1 < GNT) {
            g_store(XH[cb ^ 1], pf, tid, s4);
            __syncthreads();
        }
    }

    // channel sums (f32-exact means)
#pragma unroll
    for (int j = 0; j < 4; ++j) ssum[tid][j] = s4[j];
    __syncthreads();
    if (tid < 64) {
        float s = 0.f;
#pragma unroll
        for (int g = 0; g < 16; ++g) s += ssum[g * 16 + (tid >> 2)][tid & 3];
        g_psum[b][blk][tid] = s;
    }

    // cross-warp reduce of C, 4 tiles per round; mirror writeout (i<=j rule)
    float* scr = (float*)gsm;
    for (int round = 0; round < 5; ++round) {
        __syncthreads();
#pragma unroll
        for (int rt = 0; rt < 4; ++rt) {
            const int ti = round * 4 + rt;
            float* dst = scr + ((rt * 8 + w) * 32 + lane) * 4;
            dst[0] = C[ti][0]; dst[1] = C[ti][1];
            dst[2] = C[ti][2]; dst[3] = C[ti][3];
        }
        __syncthreads();
        for (int e = tid; e < 512; e += 256) {
            const int rt = e >> 7, idx = e & 127, ln = idx >> 2, q = idx & 3;
            const int ti = round * 4 + rt;
            float v = 0.f;
#pragma unroll
            for (int ww = 0; ww < 8; ++ww)
                v += scr[((rt * 8 + ww) * 32 + ln) * 4 + q];
            const int i = gmi(ti) * 16 + (ln >> 2) + ((q >> 1) << 3);
            const int j = gnj(ti) * 8 + (ln & 3) * 2 + (q & 1);
            if (i <= j) {
                g_part[b][blk][i * 64 + j] = v;
                g_part[b][blk][j * 64 + i] = v;
            }
        }
    }
}

// ============================================================================
// 64x64 smem matmul helpers (stride MS), packed f32x2.
// ============================================================================
__device__ __forceinline__ void mm64p8(const float* __restrict__ A,
                                       const float* __restrict__ B,
                                       unsigned long long r2[4], int i, int j0) {
#pragma unroll
    for (int q = 0; q < 4; q++) r2[q] = 0ull;
#pragma unroll 8
    for (int k = 0; k < 64; ++k) {
        unsigned long long ad = dup2f(A[i * MS + k]);
        const ulonglong2* b2 = reinterpret_cast<const ulonglong2*>(B + k * MS + j0);
        ulonglong2 x0 = b2[0], x1 = b2[1];
        ffma2(r2[0], ad, x0.x); ffma2(r2[1], ad, x0.y);
        ffma2(r2[2], ad, x1.x); ffma2(r2[3], ad, x1.y);
    }
}

__device__ __forceinline__ void mm64p4(const float* __restrict__ A,
                                       const float* __restrict__ B,
                                       unsigned long long r2[2], int i, int j0) {
    r2[0] = 0ull; r2[1] = 0ull;
#pragma unroll 8
    for (int k = 0; k < 64; ++k) {
        unsigned long long ad = dup2f(A[i * MS + k]);
        const ulonglong2* b2 = reinterpret_cast<const ulonglong2*>(B + k * MS + j0);
        ulonglong2 x0 = b2[0];
        ffma2(r2[0], ad, x0.x); ffma2(r2[1], ad, x0.y);
    }
}

// ============================================================================
// Kernel 2: fused cov-reduction + Newton-Schulz. grid BATCH, 1024 threads.
// ============================================================================
__global__ void __launch_bounds__(1024) ns_kernel() {
    extern __shared__ float dsm[];
    float* sY = dsm;
    float* sZ = sY + 64 * MS;
    float* sT = sZ + 64 * MS;
    __shared__ float mean_s[NCH];

    const int b = blockIdx.x, tid = threadIdx.x;
    const int i4 = tid >> 4, j4 = (tid & 15) * 4;            // T-phase mapping
    const int u  = tid & 511;
    const int i8 = u >> 3, j8 = (u & 7) * 8;                 // half-phase mapping

    if (tid < NCH) {
        float s = 0.f;
#pragma unroll
        for (int k = 0; k < GBLK; ++k) s += g_psum[b][k][tid];
        float m = s * (1.f / (float)HW);
        mean_s[tid] = m;
        g_mean[b][tid] = m;
    }
    __syncthreads();

    const float inv_d = 1.f / (float)(HW - 1);
    for (int e = tid; e < 4096; e += 1024) {
        float s = 0.f;
#pragma unroll
        for (int k = 0; k < GBLK; ++k) s += g_part[b][k][e];
        int i = e >> 6, j = e & 63;
        sZ[i * MS + j] = (s - (float)HW * mean_s[i] * mean_s[j]) * inv_d;
    }
    __syncthreads();

    if (tid < 64) {
        float s = 0.f;
        for (int j = 0; j < 64; ++j) s += fabsf(sZ[tid * MS + j]);
        sY[tid] = s;
    }
    __syncthreads();
    if (tid == 0) {
        float m = 0.f;
        for (int r = 0; r < 64; ++r) m = fmaxf(m, sY[r]);
        sT[0] = m;
    }
    __syncthreads();
    const float c = sT[0];
    const float inv_c = 1.f / c;
    __syncthreads();

    for (int e = tid; e < 4096; e += 1024) {
        int r = e >> 6, q = e & 63;
        float v = sZ[r * MS + q];
        sY[r * MS + q] = v * inv_c;
        sZ[r * MS + q] = (r == q) ? 1.f : 0.f;
    }
    __syncthreads();

    for (int it = 0; it < NS_ITERS; ++it) {
        // T = 1.5 I - 0.5 * Z*Y   (all 1024 threads, 4-wide)
        unsigned long long t2[2];
        mm64p4(sZ, sY, t2, i4, j4);
#pragma unroll
        for (int q = 0; q < 2; q++) {
            int j = j4 + 2 * q;
            sT[i4 * MS + j]     = ((i4 == j)     ? 1.5f : 0.f) - 0.5f * lo32(t2[q]);
            sT[i4 * MS + j + 1] = ((i4 == j + 1) ? 1.5f : 0.f) - 0.5f * hi32(t2[q]);
        }
        __syncthreads();

        // Y' = Y*T (tid<512), Z' = T*Z (tid>=512), concurrent
        unsigned long long r2[4];
        if (tid < 512) mm64p8(sY, sT, r2, i8, j8);
        else           mm64p8(sT, sZ, r2, i8, j8);
        __syncthreads();
        float* dst = (tid < 512) ? sY : sZ;
#pragma unroll
        for (int q = 0; q < 4; q++) {
            dst[i8 * MS + j8 + 2 * q]     = lo32(r2[q]);
            dst[i8 * MS + j8 + 2 * q + 1] = hi32(r2[q]);
        }
        __syncthreads();
    }

    const float sc = sqrtf(c), isc = rsqrtf(c);
    for (int e = tid; e < 4096; e += 1024) {
        int r = e >> 6, q = e & 63;
        g_half[b][e] = sY[r * MS + q] * sc;
        g_invh[b][e] = sZ[r * MS + q] * isc;
    }
}

// ============================================================================
// Kernel 3: A_b (row-major) + bias_b. grid BATCH, 512 threads.
// ============================================================================
__global__ void __launch_bounds__(512) comb_kernel(const int* __restrict__ perm,
                                                   const float* __restrict__ alpha) {
    __shared__ float sS[64 * MS], sTi[64 * MS], red[512];
    const int b = blockIdx.x, tid = threadIdx.x;
    const int pb = perm[b];
    const float al = alpha[b];
    const float oma = 1.f - al;

    for (int e = tid; e < 4096; e += 512) {
        int r = e >> 6, q = e & 63;
        sS [r * MS + q] = g_half[pb][e];
        sTi[r * MS + q] = g_invh[b][e];
    }
    __syncthreads();

    const int i = tid >> 3, j0 = (tid & 7) * 8;
    unsigned long long m2[4];
    mm64p8(sS, sTi, m2, i, j0);

    float m[8];
#pragma unroll
    for (int q = 0; q < 4; q++) { m[2 * q] = lo32(m2[q]); m[2 * q + 1] = hi32(m2[q]); }

    float pdot = 0.f;
#pragma unroll
    for (int q = 0; q < 8; q++) {
        int j = j0 + q;
        g_A[b][i * 64 + j] = ((i == j) ? al : 0.f) + oma * m[q];
        pdot += m[q] * g_mean[b][j];
    }
    red[tid] = pdot;
    __syncthreads();
    if (tid < 64) {
        float dot = 0.f;
#pragma unroll
        for (int t = 0; t < 8; t++) dot += red[tid * 8 + t];
        g_bias[b][tid] = oma * (g_mean[pb][tid] - dot);
    }
}

// ============================================================================
// Kernel 4: out = A*x + bias via mma.sync bf16 split (exact R12 kernel,
// 133us measured). grid (ABLKS, BATCH), 256 threads, 2 blocks/SM pinned.
// ============================================================================
#define SM_HX0  0
#define SM_HX1  18432
#define SM_LX0  36864
#define SM_LX1  55296
#define SM_AH   73728
#define SM_AL   82944
#define SM_BIAS 92160
#define APPLY_SMEM (SM_BIAS + 256)

__device__ __forceinline__ void stage_tile(unsigned short* hx, unsigned short* lx,
                                           const float4* __restrict__ src, int tid) {
#pragma unroll
    for (int r = 0; r < 8; ++r) {
        const int f = tid + 256 * r;
        const float4 v = src[f];
        const int px = f >> 4, k0 = (f & 15) * 4;
        unsigned short h0 = bfh(v.x), h1 = bfh(v.y), h2 = bfh(v.z), h3 = bfh(v.w);
        float r0 = v.x - __bfloat162float(__ushort_as_bfloat16(h0));
        float r1 = v.y - __bfloat162float(__ushort_as_bfloat16(h1));
        float r2 = v.z - __bfloat162float(__ushort_as_bfloat16(h2));
        float r3 = v.w - __bfloat162float(__ushort_as_bfloat16(h3));
        uint2 hp, lp;
        hp.x = (uint32_t)h0 | ((uint32_t)h1 << 16);
        hp.y = (uint32_t)h2 | ((uint32_t)h3 << 16);
        lp.x = (uint32_t)bfh(r0) | ((uint32_t)bfh(r1) << 16);
        lp.y = (uint32_t)bfh(r2) | ((uint32_t)bfh(r3) << 16);
        *reinterpret_cast<uint2*>(hx + px * XROW + k0) = hp;
        *reinterpret_cast<uint2*>(lx + px * XROW + k0) = lp;
    }
}

__global__ void __launch_bounds__(256, 2) apply_mma_kernel(const float* __restrict__ x,
                                                           float* __restrict__ out) {
    extern __shared__ char smem[];
    unsigned short* HX[2] = {(unsigned short*)(smem + SM_HX0),
                             (unsigned short*)(smem + SM_HX1)};
    unsigned short* LX[2] = {(unsigned short*)(smem + SM_LX0),
                             (unsigned short*)(smem + SM_LX1)};
    unsigned short* AH = (unsigned short*)(smem + SM_AH);
    unsigned short* AL = (unsigned short*)(smem + SM_AL);
    float* sbias = (float*)(smem + SM_BIAS);

    const int tid = threadIdx.x;
    const int w = tid >> 5, lane = tid & 31;
    const int b = blockIdx.y, blk = blockIdx.x;

    for (int e = tid; e < 4096; e += 256) {
        const int c = e >> 6, k = e & 63;
        const float a = g_A[b][e];
        unsigned short h = bfh(a);
        float rl = a - __bfloat162float(__ushort_as_bfloat16(h));
        AH[c * AROW + k] = h;
        AL[c * AROW + k] = bfh(rl);
    }
    if (tid < 64) sbias[tid] = g_bias[b][tid];

    const float4* x4 = reinterpret_cast<const float4*>(x) +
                       ((size_t)b * HW + (size_t)blk * APB) * (NCH / 4);
    float* ob = out + ((size_t)b * HW + (size_t)blk * APB) * NCH;

    stage_tile(HX[0], LX[0], x4, tid);
    __syncthreads();

    const int pxb   = (w >> 1) * 32;
    const int nbase = (w & 1) * 32;
    uint32_t Bh[4][4][2], Bl[4][4][2];
    {
        const uint32_t ah_s = smem_u32(AH), al_s = smem_u32(AL);
        const int rown = nbase + (lane & 7) + ((lane >> 4) << 3);
        const int koff = ((lane >> 3) & 1) * 8;
#pragma unroll
        for (int ks = 0; ks < 4; ++ks)
#pragma unroll
            for (int ntp = 0; ntp < 2; ++ntp) {
                const uint32_t off =
                    (uint32_t)(((rown + ntp * 16) * AROW + ks * 16 + koff) * 2);
                uint32_t rh[4], rl[4];
                ldm4(rh, ah_s + off);
                ldm4(rl, al_s + off);
                Bh[ks][ntp * 2][0] = rh[0]; Bh[ks][ntp * 2][1] = rh[1];
                Bh[ks][ntp * 2 + 1][0] = rh[2]; Bh[ks][ntp * 2 + 1][1] = rh[3];
                Bl[ks][ntp * 2][0] = rl[0]; Bl[ks][ntp * 2][1] = rl[1];
                Bl[ks][ntp * 2 + 1][0] = rl[2]; Bl[ks][ntp * 2 + 1][1] = rl[3];
            }
    }

    float2 bv[4];
    {
        const int cpair = (lane & 3) * 2;
#pragma unroll
        for (int nt = 0; nt < 4; ++nt) {
            bv[nt].x = sbias[nbase + nt * 8 + cpair];
            bv[nt].y = sbias[nbase + nt * 8 + cpair + 1];
        }
    }

    const int xrow = (lane & 15);
    const int xkof = ((lane >> 4) << 3);

    for (int t = 0; t < NTIL; ++t) {
        const int cb = t & 1;

        if (t + 1 < NTIL)
            stage_tile(HX[cb ^ 1], LX[cb ^ 1], x4 + (size_t)(t + 1) * 2048, tid);

        const uint32_t hx_s = smem_u32(HX[cb]), lx_s = smem_u32(LX[cb]);

        float C[2][4][4];
#pragma unroll
        for (int mt = 0; mt < 2; ++mt)
#pragma unroll
            for (int nt = 0; nt < 4; ++nt)
#pragma unroll
                for (int q = 0; q < 4; ++q) C[mt][nt][q] = 0.f;

#pragma unroll
        for (int ks = 0; ks < 4; ++ks) {
            uint32_t ah[2][4], al[2][4];
#pragma unroll
            for (int mt = 0; mt < 2; ++mt) {
                const uint32_t off = (uint32_t)(
                    ((pxb + mt * 16 + xrow) * XROW + ks * 16 + xkof) * 2);
                ldm4(ah[mt], hx_s + off);
                ldm4(al[mt], lx_s + off);
            }
#pragma unroll
            for (int mt = 0; mt < 2; ++mt)
#pragma unroll
                for (int nt = 0; nt < 4; ++nt) {
                    mma_bf16(C[mt][nt], ah[mt], Bh[ks][nt][0], Bh[ks][nt][1]);
                    mma_bf16(C[mt][nt], al[mt], Bh[ks][nt][0], Bh[ks][nt][1]);
                    mma_bf16(C[mt][nt], ah[mt], Bl[ks][nt][0], Bl[ks][nt][1]);
                }
        }

        const int gr = lane >> 2, cpair = (lane & 3) * 2;
        const int pxg = t * ATL + pxb + gr;
#pragma unroll
        for (int mt = 0; mt < 2; ++mt) {
            float* row0 = ob + (size_t)(pxg + mt * 16) * NCH;
            float* row1 = row0 + 8 * NCH;
#pragma unroll
            for (int nt = 0; nt < 4; ++nt) {
                const int n = nbase + nt * 8 + cpair;
                *reinterpret_cast<float2*>(row0 + n) =
                    make_float2(C[mt][nt][0] + bv[nt].x, C[mt][nt][1] + bv[nt].y);
                *reinterpret_cast<float2*>(row1 + n) =
                    make_float2(C[mt][nt][2] + bv[nt].x, C[mt][nt][3] + bv[nt].y);
            }
        }
        __syncthreads();
    }
}

// ============================================================================
extern "C" void kernel_launch(void* const* d_in, const int* in_sizes, int n_in,
                              void* d_out, int out_size) {
    (void)in_sizes; (void)n_in; (void)out_size;
    const float* x     = (const float*)d_in[0];
    const int*   perm  = (const int*)d_in[1];
    const float* alpha = (const float*)d_in[2];
    float*       out   = (float*)d_out;

    const int ns_smem   = 3 * 64 * MS * (int)sizeof(float);   // 52224 B
    const int gram_smem = 2 * 18432;                          // 36864 B
    cudaFuncSetAttribute(ns_kernel, cudaFuncAttributeMaxDynamicSharedMemorySize, ns_smem);
    cudaFuncSetAttribute(apply_mma_kernel, cudaFuncAttributeMaxDynamicSharedMemorySize,
                         APPLY_SMEM);

    gram_mma_kernel<<<dim3(GBLK, BATCH), 256, gram_smem>>>(x);
    ns_kernel<<<BATCH, 1024, ns_smem>>>();
    comb_kernel<<<BATCH, 512>>>(perm, alpha);
    apply_mma_kernel<<<dim3(ABLKS, BATCH), 256, APPLY_SMEM>>>(x, out);
}